// round 7
// baseline (speedup 1.0000x reference)
#include <cuda_runtime.h>
#include <cuda_bf16.h>
#include <cstdint>
#include <math.h>

#define BNS 0.9999950000374996f  // 1/sqrt(1+1e-5)

// ================= scratch (device globals) ================================
__device__ float g_k   [32*96*256];
__device__ float g_v   [32*384*256];
__device__ float g_w   [32*4*256];
__device__ float g_q   [4*32*96*256];
__device__ float g_res [4*32*256*384];     // res PRE-acts (E*TB,N,C)
__device__ float g_p   [32*384*256];
__device__ float g_xr  [32*384*256];
__device__ float g_h   [32*2048*256];
__device__ float g_m   [32*1024*256];
__device__ float g_f2  [32*384*256];
__device__ unsigned short g_qb[128*256*96];
__device__ unsigned short g_kb[32*256*96];
__device__ unsigned short g_vb[32*384*256];
__device__ unsigned short g_ab[128*256*256];
__device__ unsigned short g_yb[32*256*384];
__device__ unsigned short g_mb[32*256*1024];
__device__ unsigned short g_w3a[3*384*384];
__device__ unsigned short g_w3b[3*384*1024];

__device__ __forceinline__ uint32_t smem_u32(const void* p){
    uint32_t a;
    asm("{ .reg .u64 t; cvta.to.shared.u64 t, %1; cvt.u32.u64 %0, t; }" : "=r"(a) : "l"(p));
    return a;
}
#define LDMX4(r0,r1,r2,r3,ad) \
    asm volatile("ldmatrix.sync.aligned.m8n8.x4.shared.b16 {%0,%1,%2,%3}, [%4];" \
        : "=r"(r0),"=r"(r1),"=r"(r2),"=r"(r3) : "r"(ad))
#define LDMX2(r0,r1,ad) \
    asm volatile("ldmatrix.sync.aligned.m8n8.x2.shared.b16 {%0,%1}, [%2];" \
        : "=r"(r0),"=r"(r1) : "r"(ad))
#define MMA16816(c0,c1,c2,c3,a0,a1,a2,a3,b0,b1) \
    asm volatile("mma.sync.aligned.m16n8k16.row.col.f32.bf16.bf16.f32 " \
        "{%0,%1,%2,%3}, {%4,%5,%6,%7}, {%8,%9}, {%0,%1,%2,%3};" \
        : "+f"(c0),"+f"(c1),"+f"(c2),"+f"(c3) \
        : "r"(a0),"r"(a1),"r"(a2),"r"(a3),"r"(b0),"r"(b1))

// ============ SIMT GEMM, double-buffered (same math order as R1) ===========
template<bool AKF, bool BKF>
__global__ void gemm_kernel(
    const float* __restrict__ A, long aG, long aB, int sAm, int sAk,
    const float* __restrict__ B, long bG, long bB, int sBk, int sBn,
    float* __restrict__ C,
    const float* __restrict__ bias, const float* __restrict__ scale,
    const float* __restrict__ shift, int pG,
    int M, int N, int K, int Bcnt)
{
    __shared__ float As[2][16][68];
    __shared__ float Bs[2][16][68];
    int z = blockIdx.z;
    int g = z / Bcnt, b = z % Bcnt;
    A += (long)g * aG + (long)b * aB;
    B += (long)g * bG + (long)b * bB;
    C += (long)z * M * N;
    int m0 = blockIdx.y * 64;
    int n0 = blockIdx.x * 64;
    int tid = threadIdx.x;
    int tx = tid & 15, ty = tid >> 4;
    float acc[4][4] = {};
    float ra[4], rb[4];

    // prologue: tile 0 -> regs -> smem[0]
    #pragma unroll
    for (int l = 0; l < 4; l++) {
        int idx = tid + l * 256;
        int kk, i;
        if (AKF) { kk = idx & 15; i = idx >> 4; }
        else     { i = idx & 63; kk = idx >> 6; }
        int m = m0 + i;
        ra[l] = (m < M) ? A[(long)m * sAm + (long)kk * sAk] : 0.f;
    }
    #pragma unroll
    for (int l = 0; l < 4; l++) {
        int idx = tid + l * 256;
        int kk, j;
        if (BKF) { kk = idx & 15; j = idx >> 4; }
        else     { j = idx & 63; kk = idx >> 6; }
        int n = n0 + j;
        rb[l] = (n < N) ? B[(long)kk * sBk + (long)n * sBn] : 0.f;
    }
    #pragma unroll
    for (int l = 0; l < 4; l++) {
        int idx = tid + l * 256;
        int kk, i;
        if (AKF) { kk = idx & 15; i = idx >> 4; }
        else     { i = idx & 63; kk = idx >> 6; }
        As[0][kk][i] = ra[l];
    }
    #pragma unroll
    for (int l = 0; l < 4; l++) {
        int idx = tid + l * 256;
        int kk, j;
        if (BKF) { kk = idx & 15; j = idx >> 4; }
        else     { j = idx & 63; kk = idx >> 6; }
        Bs[0][kk][j] = rb[l];
    }
    __syncthreads();

    int nT = K >> 4;
    for (int t = 0; t < nT; t++) {
        int cur = t & 1;
        if (t + 1 < nT) {
            int k0 = (t + 1) << 4;
            #pragma unroll
            for (int l = 0; l < 4; l++) {
                int idx = tid + l * 256;
                int kk, i;
                if (AKF) { kk = idx & 15; i = idx >> 4; }
                else     { i = idx & 63; kk = idx >> 6; }
                int m = m0 + i;
                ra[l] = (m < M) ? A[(long)m * sAm + (long)(k0 + kk) * sAk] : 0.f;
            }
            #pragma unroll
            for (int l = 0; l < 4; l++) {
                int idx = tid + l * 256;
                int kk, j;
                if (BKF) { kk = idx & 15; j = idx >> 4; }
                else     { j = idx & 63; kk = idx >> 6; }
                int n = n0 + j;
                rb[l] = (n < N) ? B[(long)(k0 + kk) * sBk + (long)n * sBn] : 0.f;
            }
        }
        #pragma unroll
        for (int kk = 0; kk < 16; kk++) {
            float4 a4 = *(const float4*)&As[cur][kk][ty * 4];
            float4 b4 = *(const float4*)&Bs[cur][kk][tx * 4];
            float av[4] = {a4.x, a4.y, a4.z, a4.w};
            float bv[4] = {b4.x, b4.y, b4.z, b4.w};
            #pragma unroll
            for (int u = 0; u < 4; u++)
                #pragma unroll
                for (int v = 0; v < 4; v++)
                    acc[u][v] = fmaf(av[u], bv[v], acc[u][v]);
        }
        if (t + 1 < nT) {
            int nb = cur ^ 1;
            #pragma unroll
            for (int l = 0; l < 4; l++) {
                int idx = tid + l * 256;
                int kk, i;
                if (AKF) { kk = idx & 15; i = idx >> 4; }
                else     { i = idx & 63; kk = idx >> 6; }
                As[nb][kk][i] = ra[l];
            }
            #pragma unroll
            for (int l = 0; l < 4; l++) {
                int idx = tid + l * 256;
                int kk, j;
                if (BKF) { kk = idx & 15; j = idx >> 4; }
                else     { j = idx & 63; kk = idx >> 6; }
                Bs[nb][kk][j] = rb[l];
            }
        }
        __syncthreads();
    }

    #pragma unroll
    for (int u = 0; u < 4; u++) {
        int m = m0 + ty * 4 + u;
        if (m >= M) continue;
        float bi = bias  ? bias [g * pG + m]       : 0.f;
        float sc = scale ? scale[g * pG + m] * BNS : 1.f;
        float sh = shift ? shift[g * pG + m]       : 0.f;
        #pragma unroll
        for (int v = 0; v < 4; v++) {
            int n = n0 + tx * 4 + v;
            C[(long)m * N + n] = (acc[u][v] + bi) * sc + sh;
        }
    }
}

// ================= LIF kernels =============================================
// float4 in-place LIF: buf treated as float4[], M4 = elems/4 per (slab, tb)
__global__ void lif4_kernel(float4* __restrict__ buf, int slabs, long slabStride4, int M4)
{
    long tid = (long)blockIdx.x * blockDim.x + threadIdx.x;
    long total = (long)slabs * 8 * M4;
    if (tid >= total) return;
    int  j = (int)(tid % M4);
    long r = tid / M4;
    int  b = (int)(r & 7);
    int  s = (int)(r >> 3);
    float4* p = buf + (long)s * slabStride4;
    float4 mem = make_float4(0.f, 0.f, 0.f, 0.f);
    #pragma unroll
    for (int t = 0; t < 4; t++) {
        long idx = (long)(t * 8 + b) * M4 + j;
        float4 x = p[idx];
        float4 sp;
        mem.x += (x.x - mem.x) * 0.5f; sp.x = (mem.x >= 1.f) ? 1.f : 0.f; mem.x *= (1.f - sp.x);
        mem.y += (x.y - mem.y) * 0.5f; sp.y = (mem.y >= 1.f) ? 1.f : 0.f; mem.y *= (1.f - sp.y);
        mem.z += (x.z - mem.z) * 0.5f; sp.z = (mem.z >= 1.f) ? 1.f : 0.f; mem.z *= (1.f - sp.z);
        mem.w += (x.w - mem.w) * 0.5f; sp.w = (mem.w >= 1.f) ? 1.f : 0.f; mem.w *= (1.f - sp.w);
        p[idx] = sp;
    }
}

__global__ void lif_q_kernel()
{
    int tid = blockIdx.x * 256 + threadIdx.x;
    if (tid >= 4*8*96*256) return;
    int n = tid & 255;
    int c = (tid >> 8) % 96;
    int b = (tid / (256*96)) & 7;
    int e = tid / (256*96*8);
    float mem = 0.f;
    #pragma unroll
    for (int t = 0; t < 4; t++) {
        int eb = e*32 + t*8 + b;
        float x = g_q[((long)eb*96 + c)*256 + n];
        mem = mem + (x - mem) * 0.5f;
        unsigned short sp = (mem >= 1.f) ? 0x3F80 : 0;
        mem *= (sp ? 0.f : 1.f);
        g_qb[((long)eb*256 + n)*96 + c] = sp;
    }
}
__global__ void lif_k_kernel()
{
    int tid = blockIdx.x * 256 + threadIdx.x;
    if (tid >= 8*96*256) return;
    int m = tid & 255;
    int c = (tid >> 8) % 96;
    int b = tid / (256*96);
    float mem = 0.f;
    #pragma unroll
    for (int t = 0; t < 4; t++) {
        int tb = t*8 + b;
        float x = g_k[((long)tb*96 + c)*256 + m];
        mem = mem + (x - mem) * 0.5f;
        unsigned short sp = (mem >= 1.f) ? 0x3F80 : 0;
        mem *= (sp ? 0.f : 1.f);
        g_kb[((long)tb*256 + m)*96 + c] = sp;
    }
}
__global__ void lif_v_kernel()
{
    int tid = blockIdx.x * 256 + threadIdx.x;
    if (tid >= 8*384*256) return;
    int m = tid & 255;
    int d = (tid >> 8) % 384;
    int b = tid / (256*384);
    float mem = 0.f;
    #pragma unroll
    for (int t = 0; t < 4; t++) {
        int tb = t*8 + b;
        long idx = ((long)tb*384 + d)*256 + m;
        float x = g_v[idx];
        mem = mem + (x - mem) * 0.5f;
        unsigned short sp = (mem >= 1.f) ? 0x3F80 : 0;
        mem *= (sp ? 0.f : 1.f);
        g_vb[idx] = sp;
    }
}

// ================= attn via mma.sync =======================================
__global__ __launch_bounds__(256) void attn_mma_kernel()
{
    extern __shared__ unsigned short sm[];    // As[128][104], Bs[128][104]
    unsigned short* As = sm;
    unsigned short* Bs = sm + 128*104;
    int mt = blockIdx.x, nt = blockIdx.y, eb = blockIdx.z;
    int tb = eb & 31;
    int tid = threadIdx.x, lane = tid & 31, warp = tid >> 5;

    const uint4* gq = (const uint4*)(g_qb + ((long)eb*256 + nt*128)*96);
    for (int idx = tid; idx < 1536; idx += 256) {
        int i = idx / 12, s = idx % 12;
        *(uint4*)(As + i*104 + s*8) = gq[idx];
    }
    const uint4* gk = (const uint4*)(g_kb + ((long)tb*256 + mt*128)*96);
    for (int idx = tid; idx < 1536; idx += 256) {
        int i = idx / 12, s = idx % 12;
        *(uint4*)(Bs + i*104 + s*8) = gk[idx];
    }
    __syncthreads();

    int wn = (warp >> 2) * 64, wm = (warp & 3) * 32;
    float acc[4][4][4] = {};
    uint32_t base = smem_u32(sm);
    int aRow = lane & 15, aK = (lane >> 4) * 8;
    int bRow = lane & 7,  bK = ((lane >> 3) & 1) * 8;

    #pragma unroll
    for (int kt = 0; kt < 6; kt++) {
        uint32_t a[4][4], bf[4][2];
        #pragma unroll
        for (int r = 0; r < 4; r++) {
            uint32_t ad = base + (uint32_t)(((wn + r*16 + aRow)*104 + kt*16 + aK) * 2);
            LDMX4(a[r][0], a[r][1], a[r][2], a[r][3], ad);
        }
        #pragma unroll
        for (int c = 0; c < 4; c++) {
            uint32_t ad = base + (uint32_t)((128*104 + (wm + c*8 + bRow)*104 + kt*16 + bK) * 2);
            LDMX2(bf[c][0], bf[c][1], ad);
        }
        #pragma unroll
        for (int r = 0; r < 4; r++)
            #pragma unroll
            for (int c = 0; c < 4; c++)
                MMA16816(acc[r][c][0], acc[r][c][1], acc[r][c][2], acc[r][c][3],
                         a[r][0], a[r][1], a[r][2], a[r][3], bf[c][0], bf[c][1]);
    }

    unsigned short* ga = g_ab + (long)eb * 65536;
    #pragma unroll
    for (int r = 0; r < 4; r++) {
        int n = nt*128 + wn + r*16 + (lane >> 2);
        #pragma unroll
        for (int c = 0; c < 4; c++) {
            int m = mt*128 + wm + c*8 + (lane & 3)*2;
            uint32_t p0 = (uint32_t)__bfloat16_as_ushort(__float2bfloat16(acc[r][c][0]))
                        | ((uint32_t)__bfloat16_as_ushort(__float2bfloat16(acc[r][c][1])) << 16);
            uint32_t p1 = (uint32_t)__bfloat16_as_ushort(__float2bfloat16(acc[r][c][2]))
                        | ((uint32_t)__bfloat16_as_ushort(__float2bfloat16(acc[r][c][3])) << 16);
            *(uint32_t*)(ga + (long)n*256 + m)       = p0;
            *(uint32_t*)(ga + (long)(n+8)*256 + m)   = p1;
        }
    }
}

// ================= res via mma.sync ========================================
__global__ __launch_bounds__(256) void res_mma_kernel()
{
    __shared__ unsigned short As[128*72];
    __shared__ unsigned short Bs[128*72];
    int dt = blockIdx.x, nt = blockIdx.y, eb = blockIdx.z;
    int tb = eb & 31;
    int tid = threadIdx.x, lane = tid & 31, warp = tid >> 5;
    int wn = (warp >> 2) * 64, wm = (warp & 3) * 32;
    float acc[4][4][4] = {};
    uint32_t baseA = smem_u32(As), baseB = smem_u32(Bs);
    int aRow = lane & 15, aK = (lane >> 4) * 8;
    int bRow = lane & 7,  bK = ((lane >> 3) & 1) * 8;

    for (int ch = 0; ch < 4; ch++) {
        const uint4* gA = (const uint4*)(g_ab + ((long)eb*256 + nt*128)*256 + ch*64);
        for (int idx = tid; idx < 1024; idx += 256) {
            int i = idx >> 3, s = idx & 7;
            *(uint4*)(As + i*72 + s*8) = gA[i*32 + s];
        }
        const uint4* gB = (const uint4*)(g_vb + ((long)tb*384 + dt*128)*256 + ch*64);
        for (int idx = tid; idx < 1024; idx += 256) {
            int i = idx >> 3, s = idx & 7;
            *(uint4*)(Bs + i*72 + s*8) = gB[i*32 + s];
        }
        __syncthreads();
        #pragma unroll
        for (int kt = 0; kt < 4; kt++) {
            uint32_t a[4][4], bf[4][2];
            #pragma unroll
            for (int r = 0; r < 4; r++) {
                uint32_t ad = baseA + (uint32_t)(((wn + r*16 + aRow)*72 + kt*16 + aK) * 2);
                LDMX4(a[r][0], a[r][1], a[r][2], a[r][3], ad);
            }
            #pragma unroll
            for (int c = 0; c < 4; c++) {
                uint32_t ad = baseB + (uint32_t)(((wm + c*8 + bRow)*72 + kt*16 + bK) * 2);
                LDMX2(bf[c][0], bf[c][1], ad);
            }
            #pragma unroll
            for (int r = 0; r < 4; r++)
                #pragma unroll
                for (int c = 0; c < 4; c++)
                    MMA16816(acc[r][c][0], acc[r][c][1], acc[r][c][2], acc[r][c][3],
                             a[r][0], a[r][1], a[r][2], a[r][3], bf[c][0], bf[c][1]);
        }
        __syncthreads();
    }

    #pragma unroll
    for (int r = 0; r < 4; r++) {
        int n = nt*128 + wn + r*16 + (lane >> 2);
        #pragma unroll
        for (int c = 0; c < 4; c++) {
            int d = dt*128 + wm + c*8 + (lane & 3)*2;
            float2 v0 = make_float2(acc[r][c][0], acc[r][c][1]);
            float2 v1 = make_float2(acc[r][c][2], acc[r][c][3]);
            *(float2*)(g_res + ((long)eb*256 + n)*384 + d)     = v0;
            *(float2*)(g_res + ((long)eb*256 + n + 8)*384 + d) = v1;
        }
    }
}

// ========== exact-fp32 linear via 3-split bf16 mma =========================
__global__ __launch_bounds__(256) void wmma_lin_kernel(
    const unsigned short* __restrict__ A3, const unsigned short* __restrict__ Bb,
    float* __restrict__ outF,
    const float* __restrict__ bias, const float* __restrict__ scale,
    const float* __restrict__ shift, int M, int K)
{
    __shared__ unsigned short As[3*128*40];
    __shared__ unsigned short Bs[128*40];
    int mt = blockIdx.x, nt = blockIdx.y, z = blockIdx.z;
    int tid = threadIdx.x, lane = tid & 31, warp = tid >> 5;
    int m0 = mt * 128;
    int wn = (warp >> 2) * 64, wm = (warp & 3) * 32;
    float acc[4][4][4] = {};
    uint32_t baseA = smem_u32(As), baseB = smem_u32(Bs);
    int aRow = lane & 15, aK = (lane >> 4) * 8;
    int bRow = lane & 7,  bK = ((lane >> 3) & 1) * 8;

    for (int k0 = 0; k0 < K; k0 += 32) {
        for (int idx = tid; idx < 1536; idx += 256) {
            int s = idx / 512, r = idx % 512;
            int i = r >> 2, p4 = r & 3;
            *(uint4*)(As + (s*128 + i)*40 + p4*8) =
                *(const uint4*)(A3 + ((long)s*M + m0 + i)*K + k0 + p4*8);
        }
        for (int idx = tid; idx < 512; idx += 256) {
            int i = idx >> 2, p4 = idx & 3;
            *(uint4*)(Bs + i*40 + p4*8) =
                *(const uint4*)(Bb + ((long)z*256 + nt*128 + i)*K + k0 + p4*8);
        }
        __syncthreads();
        #pragma unroll
        for (int kt = 0; kt < 2; kt++) {
            uint32_t bf[4][2];
            #pragma unroll
            for (int c = 0; c < 4; c++) {
                uint32_t ad = baseB + (uint32_t)(((wm + c*8 + bRow)*40 + kt*16 + bK) * 2);
                LDMX2(bf[c][0], bf[c][1], ad);
            }
            #pragma unroll
            for (int s = 0; s < 3; s++) {
                uint32_t a[4][4];
                #pragma unroll
                for (int r = 0; r < 4; r++) {
                    uint32_t ad = baseA + (uint32_t)(((s*128 + wn + r*16 + aRow)*40 + kt*16 + aK) * 2);
                    LDMX4(a[r][0], a[r][1], a[r][2], a[r][3], ad);
                }
                #pragma unroll
                for (int r = 0; r < 4; r++)
                    #pragma unroll
                    for (int c = 0; c < 4; c++)
                        MMA16816(acc[r][c][0], acc[r][c][1], acc[r][c][2], acc[r][c][3],
                                 a[r][0], a[r][1], a[r][2], a[r][3], bf[c][0], bf[c][1]);
            }
        }
        __syncthreads();
    }

    #pragma unroll
    for (int r = 0; r < 4; r++) {
        int m  = m0 + wn + r*16 + (lane >> 2);
        float bi0 = bias[m],   sc0 = scale[m]   * BNS, sh0 = shift[m];
        float bi1 = bias[m+8], sc1 = scale[m+8] * BNS, sh1 = shift[m+8];
        #pragma unroll
        for (int c = 0; c < 4; c++) {
            int n = nt*128 + wm + c*8 + (lane & 3)*2;
            float2 v0, v1;
            v0.x = (acc[r][c][0] + bi0) * sc0 + sh0;
            v0.y = (acc[r][c][1] + bi0) * sc0 + sh0;
            v1.x = (acc[r][c][2] + bi1) * sc1 + sh1;
            v1.y = (acc[r][c][3] + bi1) * sc1 + sh1;
            *(float2*)(outF + ((long)z*M + m)*256 + n)     = v0;
            *(float2*)(outF + ((long)z*M + m + 8)*256 + n) = v1;
        }
    }
}

// ================= helper kernels ==========================================
__global__ void wsplit3_kernel(const float* __restrict__ w, unsigned short* __restrict__ w3, int total)
{
    int i = blockIdx.x * 256 + threadIdx.x;
    if (i >= total) return;
    float x = w[i];
    __nv_bfloat16 h0 = __float2bfloat16(x);
    float r1 = x - __bfloat162float(h0);
    __nv_bfloat16 h1 = __float2bfloat16(r1);
    float r2 = r1 - __bfloat162float(h1);
    __nv_bfloat16 h2 = __float2bfloat16(r2);
    w3[i]             = __bfloat16_as_ushort(h0);
    w3[total + i]     = __bfloat16_as_ushort(h1);
    w3[2 * total + i] = __bfloat16_as_ushort(h2);
}

// fused res-LIF + router combine: reads res PRE-acts, emits bf16 y (exact ints)
__global__ void combine_lif_kernel()
{
    long tid = (long)blockIdx.x * 256 + threadIdx.x;
    if (tid >= (long)8 * 256 * 384) return;
    int d = (int)(tid % 384);
    int n = (int)((tid / 384) % 256);
    int b = (int)(tid / (384 * 256));
    float y[4] = {0.f, 0.f, 0.f, 0.f};
    #pragma unroll
    for (int e = 0; e < 4; e++) {
        float mem = 0.f;
        #pragma unroll
        for (int t = 0; t < 4; t++) {
            int eb = e * 32 + t * 8 + b;
            float pre = g_res[((long)eb * 256 + n) * 384 + d];
            mem = mem + (pre - mem) * 0.5f;
            float sp = (mem >= 1.f) ? 1.f : 0.f;
            mem *= (1.f - sp);
            y[t] = fmaf(g_w[((t * 8 + b) * 4 + e) * 256 + n], sp, y[t]);
        }
    }
    #pragma unroll
    for (int t = 0; t < 4; t++)
        g_yb[((long)(t * 8 + b) * 256 + n) * 384 + d] =
            __bfloat16_as_ushort(__float2bfloat16(y[t]));
}

__global__ void transpose_m_kernel()
{
    __shared__ unsigned short tile[32][33];
    int c0 = blockIdx.x * 32, n0 = blockIdx.y * 32, tb = blockIdx.z;
    int tx = threadIdx.x & 31, ty = threadIdx.x >> 5;
    #pragma unroll
    for (int p = 0; p < 4; p++) {
        int c = c0 + ty + p*8;
        tile[ty + p*8][tx] = __bfloat16_as_ushort(
            __float2bfloat16(g_m[((long)tb*1024 + c)*256 + n0 + tx]));
    }
    __syncthreads();
    #pragma unroll
    for (int p = 0; p < 4; p++) {
        int n = n0 + ty + p*8;
        g_mb[((long)tb*256 + n)*1024 + c0 + tx] = tile[tx][ty + p*8];
    }
}

__global__ void add_kernel(const float* __restrict__ a, const float* __restrict__ b,
                           float* __restrict__ o, int n)
{
    int i = blockIdx.x * 256 + threadIdx.x;
    if (i < n) o[i] = a[i] + b[i];
}

__global__ void dwconv_gate_kernel(const float* __restrict__ dw_w, const float* __restrict__ dw_b,
                                   const float* __restrict__ dw_g, const float* __restrict__ dw_be)
{
    int tid = blockIdx.x * 256 + threadIdx.x;
    if (tid >= 8 * 1024 * 256) return;
    int n  = tid & 255;
    int c  = (tid >> 8) & 1023;
    int b  = tid >> 18;
    int hh = n >> 4, ww = n & 15;
    float wk[9];
    #pragma unroll
    for (int i = 0; i < 9; i++) wk[i] = dw_w[c * 9 + i];
    float bi = dw_b[c], sc = dw_g[c] * BNS, sh = dw_be[c];
    float mem = 0.f;
    #pragma unroll
    for (int t = 0; t < 4; t++) {
        int tb = t * 8 + b;
        const float* x1 = g_h + ((long)tb * 2048 + c) * 256;
        float acc = bi;
        #pragma unroll
        for (int di = 0; di < 3; di++) {
            int yy = hh + di - 1;
            if (yy < 0 || yy > 15) continue;
            #pragma unroll
            for (int dj = 0; dj < 3; dj++) {
                int xx = ww + dj - 1;
                if (xx < 0 || xx > 15) continue;
                acc = fmaf(wk[di * 3 + dj], x1[yy * 16 + xx], acc);
            }
        }
        float pre = acc * sc + sh;
        mem = mem + (pre - mem) * 0.5f;
        float sp = (mem >= 1.f) ? 1.f : 0.f;
        mem *= (1.f - sp);
        float x2 = g_h[((long)tb * 2048 + 1024 + c) * 256 + n];
        g_m[((long)tb * 1024 + c) * 256 + n] = sp * x2;
    }
}

// ===========================================================================
extern "C" void kernel_launch(void* const* d_in, const int* in_sizes, int n_in,
                              void* d_out, int out_size)
{
    const float* x         = (const float*)d_in[0];
    const float* k_w       = (const float*)d_in[2];
    const float* v_w       = (const float*)d_in[3];
    const float* router_w  = (const float*)d_in[4];
    const float* router_b  = (const float*)d_in[5];
    const float* router_g  = (const float*)d_in[6];
    const float* router_be = (const float*)d_in[7];
    const float* exp_w     = (const float*)d_in[8];
    const float* exp_g     = (const float*)d_in[9];
    const float* exp_b     = (const float*)d_in[10];
    const float* proj_w    = (const float*)d_in[11];
    const float* proj_b    = (const float*)d_in[12];
    const float* proj_g    = (const float*)d_in[13];
    const float* proj_be   = (const float*)d_in[14];
    const float* fc1_w     = (const float*)d_in[15];
    const float* fc1_b     = (const float*)d_in[16];
    const float* fc1_g     = (const float*)d_in[17];
    const float* fc1_be    = (const float*)d_in[18];
    const float* dw_w      = (const float*)d_in[19];
    const float* dw_b      = (const float*)d_in[20];
    const float* dw_g      = (const float*)d_in[21];
    const float* dw_be     = (const float*)d_in[22];
    const float* fc2_w     = (const float*)d_in[23];
    const float* fc2_b     = (const float*)d_in[24];
    const float* fc2_g     = (const float*)d_in[25];
    const float* fc2_be    = (const float*)d_in[26];
    float* out = (float*)d_out;

    float *pk, *pv, *pw, *pq, *pp, *pxr, *ph, *pm, *pf2, *pres;
    unsigned short *pqb, *pkb, *pvb, *pyb, *pmb, *pw3a, *pw3b;
    cudaGetSymbolAddress((void**)&pk,   g_k);
    cudaGetSymbolAddress((void**)&pv,   g_v);
    cudaGetSymbolAddress((void**)&pw,   g_w);
    cudaGetSymbolAddress((void**)&pq,   g_q);
    cudaGetSymbolAddress((void**)&pres, g_res);
    cudaGetSymbolAddress((void**)&pp,   g_p);
    cudaGetSymbolAddress((void**)&pxr,  g_xr);
    cudaGetSymbolAddress((void**)&ph,   g_h);
    cudaGetSymbolAddress((void**)&pm,   g_m);
    cudaGetSymbolAddress((void**)&pf2,  g_f2);
    cudaGetSymbolAddress((void**)&pqb,  g_qb);
    cudaGetSymbolAddress((void**)&pkb,  g_kb);
    cudaGetSymbolAddress((void**)&pvb,  g_vb);
    cudaGetSymbolAddress((void**)&pyb,  g_yb);
    cudaGetSymbolAddress((void**)&pmb,  g_mb);
    cudaGetSymbolAddress((void**)&pw3a, g_w3a);
    cudaGetSymbolAddress((void**)&pw3b, g_w3b);

    cudaFuncSetAttribute(attn_mma_kernel, cudaFuncAttributeMaxDynamicSharedMemorySize, 53248);

    const long XB = 384 * 256;
    dim3 blk(256);

    // weight splits
    wsplit3_kernel<<<(384*384+255)/256,blk>>>(proj_w, pw3a, 384*384);
    wsplit3_kernel<<<(384*1024+255)/256,blk>>>(fc2_w, pw3b, 384*1024);

    // --- SSA pre-activations (double-buffered SIMT fp32) ---
    gemm_kernel<true,false><<<dim3(4,2,32),blk>>>(k_w,0,0,384,1, x,0,XB,256,1,
        pk, nullptr,nullptr,nullptr,0, 96,256,384,32);
    gemm_kernel<true,false><<<dim3(4,6,32),blk>>>(v_w,0,0,384,1, x,0,XB,256,1,
        pv, nullptr,nullptr,nullptr,0, 384,256,384,32);
    gemm_kernel<true,false><<<dim3(4,1,32),blk>>>(router_w,0,0,384,1, x,0,XB,256,1,
        pw, router_b,router_g,router_be,0, 4,256,384,32);
    gemm_kernel<true,false><<<dim3(4,2,128),blk>>>(exp_w,(long)96*384,0,384,1, x,0,XB,256,1,
        pq, nullptr,exp_g,exp_b,96, 96,256,384,32);

    // --- LIF -> bf16 spikes in mma layouts ---
    lif_k_kernel<<<(8*96*256+255)/256,blk>>>();
    lif_v_kernel<<<(8*384*256+255)/256,blk>>>();
    lif4_kernel<<<(8*256+255)/256,blk>>>((float4*)pw, 1, 0, 256);
    lif_q_kernel<<<(4*8*96*256+255)/256,blk>>>();

    // --- tensor-core attention ---
    attn_mma_kernel<<<dim3(2,2,128),blk,53248>>>();
    res_mma_kernel<<<dim3(3,2,128),blk>>>();

    // fused res-LIF + combine -> bf16 y
    combine_lif_kernel<<<(8*256*384+255)/256,blk>>>();

    // proj on tensor cores -> fp32 pre-acts -> LIF
    wmma_lin_kernel<<<dim3(3,2,32),blk>>>(pw3a, pyb, pp, proj_b, proj_g, proj_be, 384, 384);
    lif4_kernel<<<(8*24576+255)/256,blk>>>((float4*)pp, 1, 0, 24576);
    add_kernel<<<(32*384*256+255)/256,blk>>>(x, pp, pxr, 32*384*256);

    // --- MLP ---
    gemm_kernel<true,false><<<dim3(4,32,32),blk>>>(fc1_w,0,0,384,1, pxr,0,XB,256,1,
        ph, fc1_b,fc1_g,fc1_be,0, 2048,256,384,32);
    lif4_kernel<<<(8*131072+255)/256,blk>>>((float4*)ph, 1, 0, 131072);
    dwconv_gate_kernel<<<(8*1024*256+255)/256,blk>>>(dw_w, dw_b, dw_g, dw_be);
    transpose_m_kernel<<<dim3(32,8,32),blk>>>();

    // fc2 on tensor cores -> fp32 pre-acts -> LIF
    wmma_lin_kernel<<<dim3(3,2,32),blk>>>(pw3b, pmb, pf2, fc2_b, fc2_g, fc2_be, 384, 1024);
    lif4_kernel<<<(8*24576+255)/256,blk>>>((float4*)pf2, 1, 0, 24576);

    add_kernel<<<(32*384*256+255)/256,blk>>>(pxr, pf2, out, 32*384*256);
}

// round 8
// speedup vs baseline: 1.1415x; 1.1415x over previous
#include <cuda_runtime.h>
#include <cuda_bf16.h>
#include <cstdint>
#include <math.h>

#define BNS 0.9999950000374996f  // 1/sqrt(1+1e-5)

// ================= scratch (device globals) ================================
__device__ float g_k   [32*96*256];
__device__ float g_v   [32*384*256];
__device__ float g_w   [32*4*256];
__device__ float g_q   [4*32*96*256];
__device__ float g_res [4*32*256*384];     // res PRE-acts (E*TB,N,C)
__device__ float g_p   [32*384*256];
__device__ float g_xr  [32*384*256];
__device__ float g_h   [32*2048*256];
__device__ float g_m   [32*1024*256];
__device__ float g_f2  [32*384*256];
__device__ unsigned short g_qb[128*256*96];
__device__ unsigned short g_kb[32*256*96];
__device__ unsigned short g_vb[32*384*256];
__device__ unsigned short g_ab[128*256*256];
__device__ unsigned short g_yb[32*256*384];
__device__ unsigned short g_mb[32*256*1024];
__device__ unsigned short g_w3a[3*384*384];
__device__ unsigned short g_w3b[3*384*1024];

__device__ __forceinline__ uint32_t smem_u32(const void* p){
    uint32_t a;
    asm("{ .reg .u64 t; cvta.to.shared.u64 t, %1; cvt.u32.u64 %0, t; }" : "=r"(a) : "l"(p));
    return a;
}
#define LDMX4(r0,r1,r2,r3,ad) \
    asm volatile("ldmatrix.sync.aligned.m8n8.x4.shared.b16 {%0,%1,%2,%3}, [%4];" \
        : "=r"(r0),"=r"(r1),"=r"(r2),"=r"(r3) : "r"(ad))
#define LDMX2(r0,r1,ad) \
    asm volatile("ldmatrix.sync.aligned.m8n8.x2.shared.b16 {%0,%1}, [%2];" \
        : "=r"(r0),"=r"(r1) : "r"(ad))
#define MMA16816(c0,c1,c2,c3,a0,a1,a2,a3,b0,b1) \
    asm volatile("mma.sync.aligned.m16n8k16.row.col.f32.bf16.bf16.f32 " \
        "{%0,%1,%2,%3}, {%4,%5,%6,%7}, {%8,%9}, {%0,%1,%2,%3};" \
        : "+f"(c0),"+f"(c1),"+f"(c2),"+f"(c3) \
        : "r"(a0),"r"(a1),"r"(a2),"r"(a3),"r"(b0),"r"(b1))

// ================= SIMT GEMM (R6 exact, known good) ========================
template<bool AKF, bool BKF>
__global__ void gemm_kernel(
    const float* __restrict__ A, long aG, long aB, int sAm, int sAk,
    const float* __restrict__ B, long bG, long bB, int sBk, int sBn,
    float* __restrict__ C,
    const float* __restrict__ bias, const float* __restrict__ scale,
    const float* __restrict__ shift, int pG,
    int M, int N, int K, int Bcnt)
{
    __shared__ float As[16][68];
    __shared__ float Bs[16][68];
    int z = blockIdx.z;
    int g = z / Bcnt, b = z % Bcnt;
    A += (long)g * aG + (long)b * aB;
    B += (long)g * bG + (long)b * bB;
    C += (long)z * M * N;
    int m0 = blockIdx.y * 64;
    int n0 = blockIdx.x * 64;
    int tid = threadIdx.x;
    int tx = tid & 15, ty = tid >> 4;
    float acc[4][4] = {};
    for (int k0 = 0; k0 < K; k0 += 16) {
        #pragma unroll
        for (int l = 0; l < 4; l++) {
            int idx = tid + l * 256;
            {
                int kk, i;
                if (AKF) { kk = idx & 15; i = idx >> 4; }
                else     { i = idx & 63; kk = idx >> 6; }
                int m = m0 + i;
                As[kk][i] = (m < M) ? A[(long)m * sAm + (long)(k0 + kk) * sAk] : 0.f;
            }
            {
                int kk, j;
                if (BKF) { kk = idx & 15; j = idx >> 4; }
                else     { j = idx & 63; kk = idx >> 6; }
                int n = n0 + j;
                Bs[kk][j] = (n < N) ? B[(long)(k0 + kk) * sBk + (long)n * sBn] : 0.f;
            }
        }
        __syncthreads();
        #pragma unroll
        for (int kk = 0; kk < 16; kk++) {
            float4 a4 = *(const float4*)&As[kk][ty * 4];
            float4 b4 = *(const float4*)&Bs[kk][tx * 4];
            float av[4] = {a4.x, a4.y, a4.z, a4.w};
            float bv[4] = {b4.x, b4.y, b4.z, b4.w};
            #pragma unroll
            for (int u = 0; u < 4; u++)
                #pragma unroll
                for (int v = 0; v < 4; v++)
                    acc[u][v] = fmaf(av[u], bv[v], acc[u][v]);
        }
        __syncthreads();
    }
    #pragma unroll
    for (int u = 0; u < 4; u++) {
        int m = m0 + ty * 4 + u;
        if (m >= M) continue;
        float bi = bias  ? bias [g * pG + m]       : 0.f;
        float sc = scale ? scale[g * pG + m] * BNS : 1.f;
        float sh = shift ? shift[g * pG + m]       : 0.f;
        #pragma unroll
        for (int v = 0; v < 4; v++) {
            int n = n0 + tx * 4 + v;
            C[(long)m * N + n] = (acc[u][v] + bi) * sc + sh;
        }
    }
}

// ============ SIMT GEMM, 2 z-slabs sharing one A tile, vector loads ========
// N fixed 256, B row-major [k][256] (n contiguous), A [M][K] k-contiguous.
// slabs: slab0 = g*32 + p, slab1 = slab0 + 16 (p = bz & 15, g = bz >> 4)
__global__ __launch_bounds__(256) void gemm_z2_kernel(
    const float* __restrict__ A, long aG,
    const float* __restrict__ B, long bSlab,
    float* __restrict__ C,
    const float* __restrict__ bias, const float* __restrict__ scale,
    const float* __restrict__ shift, int pG,
    int M, int K)
{
    __shared__ float As[16][68];
    __shared__ float Bs[2][16][68];
    int bz = blockIdx.z;
    int g = bz >> 4, p = bz & 15;
    const float* Ap = A + (long)g * aG;
    const float* Bp0 = B + (long)p * bSlab;
    const float* Bp1 = B + (long)(p + 16) * bSlab;
    int m0 = blockIdx.y * 64, n0 = blockIdx.x * 64;
    int tid = threadIdx.x, tx = tid & 15, ty = tid >> 4;
    float acc[2][4][4] = {};

    int am = tid >> 2, ak = (tid & 3) * 4;     // A: 1 float4 per thread
    int bk = tid >> 4, bn = (tid & 15) * 4;    // B: 1 float4 per slab per thread

    for (int k0 = 0; k0 < K; k0 += 16) {
        float4 a4 = make_float4(0.f, 0.f, 0.f, 0.f);
        if (m0 + am < M) a4 = *(const float4*)&Ap[(long)(m0 + am) * K + k0 + ak];
        long boff = (long)(k0 + bk) * 256 + n0 + bn;
        float4 v0 = *(const float4*)&Bp0[boff];
        float4 v1 = *(const float4*)&Bp1[boff];
        As[ak + 0][am] = a4.x;
        As[ak + 1][am] = a4.y;
        As[ak + 2][am] = a4.z;
        As[ak + 3][am] = a4.w;
        *(float4*)&Bs[0][bk][bn] = v0;
        *(float4*)&Bs[1][bk][bn] = v1;
        __syncthreads();
        #pragma unroll
        for (int kk = 0; kk < 16; kk++) {
            float4 av4 = *(const float4*)&As[kk][ty * 4];
            float av[4] = {av4.x, av4.y, av4.z, av4.w};
            #pragma unroll
            for (int s = 0; s < 2; s++) {
                float4 bv4 = *(const float4*)&Bs[s][kk][tx * 4];
                float bv[4] = {bv4.x, bv4.y, bv4.z, bv4.w};
                #pragma unroll
                for (int u = 0; u < 4; u++)
                    #pragma unroll
                    for (int v = 0; v < 4; v++)
                        acc[s][u][v] = fmaf(av[u], bv[v], acc[s][u][v]);
            }
        }
        __syncthreads();
    }

    #pragma unroll
    for (int s = 0; s < 2; s++) {
        long slab = (long)g * 32 + p + s * 16;
        #pragma unroll
        for (int u = 0; u < 4; u++) {
            int m = m0 + ty * 4 + u;
            if (m >= M) continue;
            float bi = bias  ? bias [g * pG + m]       : 0.f;
            float sc = scale ? scale[g * pG + m] * BNS : 1.f;
            float sh = shift ? shift[g * pG + m]       : 0.f;
            float4 o;
            o.x = (acc[s][u][0] + bi) * sc + sh;
            o.y = (acc[s][u][1] + bi) * sc + sh;
            o.z = (acc[s][u][2] + bi) * sc + sh;
            o.w = (acc[s][u][3] + bi) * sc + sh;
            *(float4*)&C[slab * M * 256 + (long)m * 256 + n0 + tx * 4] = o;
        }
    }
}

// ================= LIF kernels =============================================
__global__ void lif4_kernel(float4* __restrict__ buf, int slabs, long slabStride4, int M4)
{
    long tid = (long)blockIdx.x * blockDim.x + threadIdx.x;
    long total = (long)slabs * 8 * M4;
    if (tid >= total) return;
    int  j = (int)(tid % M4);
    long r = tid / M4;
    int  b = (int)(r & 7);
    int  s = (int)(r >> 3);
    float4* p = buf + (long)s * slabStride4;
    float4 mem = make_float4(0.f, 0.f, 0.f, 0.f);
    #pragma unroll
    for (int t = 0; t < 4; t++) {
        long idx = (long)(t * 8 + b) * M4 + j;
        float4 x = p[idx];
        float4 sp;
        mem.x += (x.x - mem.x) * 0.5f; sp.x = (mem.x >= 1.f) ? 1.f : 0.f; mem.x *= (1.f - sp.x);
        mem.y += (x.y - mem.y) * 0.5f; sp.y = (mem.y >= 1.f) ? 1.f : 0.f; mem.y *= (1.f - sp.y);
        mem.z += (x.z - mem.z) * 0.5f; sp.z = (mem.z >= 1.f) ? 1.f : 0.f; mem.z *= (1.f - sp.z);
        mem.w += (x.w - mem.w) * 0.5f; sp.w = (mem.w >= 1.f) ? 1.f : 0.f; mem.w *= (1.f - sp.w);
        p[idx] = sp;
    }
}

__global__ void lif_q_kernel()
{
    int tid = blockIdx.x * 256 + threadIdx.x;
    if (tid >= 4*8*96*256) return;
    int n = tid & 255;
    int c = (tid >> 8) % 96;
    int b = (tid / (256*96)) & 7;
    int e = tid / (256*96*8);
    float mem = 0.f;
    #pragma unroll
    for (int t = 0; t < 4; t++) {
        int eb = e*32 + t*8 + b;
        float x = g_q[((long)eb*96 + c)*256 + n];
        mem = mem + (x - mem) * 0.5f;
        unsigned short sp = (mem >= 1.f) ? 0x3F80 : 0;
        mem *= (sp ? 0.f : 1.f);
        g_qb[((long)eb*256 + n)*96 + c] = sp;
    }
}
__global__ void lif_k_kernel()
{
    int tid = blockIdx.x * 256 + threadIdx.x;
    if (tid >= 8*96*256) return;
    int m = tid & 255;
    int c = (tid >> 8) % 96;
    int b = tid / (256*96);
    float mem = 0.f;
    #pragma unroll
    for (int t = 0; t < 4; t++) {
        int tb = t*8 + b;
        float x = g_k[((long)tb*96 + c)*256 + m];
        mem = mem + (x - mem) * 0.5f;
        unsigned short sp = (mem >= 1.f) ? 0x3F80 : 0;
        mem *= (sp ? 0.f : 1.f);
        g_kb[((long)tb*256 + m)*96 + c] = sp;
    }
}
__global__ void lif_v_kernel()
{
    int tid = blockIdx.x * 256 + threadIdx.x;
    if (tid >= 8*384*256) return;
    int m = tid & 255;
    int d = (tid >> 8) % 384;
    int b = tid / (256*384);
    float mem = 0.f;
    #pragma unroll
    for (int t = 0; t < 4; t++) {
        int tb = t*8 + b;
        long idx = ((long)tb*384 + d)*256 + m;
        float x = g_v[idx];
        mem = mem + (x - mem) * 0.5f;
        unsigned short sp = (mem >= 1.f) ? 0x3F80 : 0;
        mem *= (sp ? 0.f : 1.f);
        g_vb[idx] = sp;
    }
}

// ================= attn via mma.sync =======================================
__global__ __launch_bounds__(256) void attn_mma_kernel()
{
    extern __shared__ unsigned short sm[];    // As[128][104], Bs[128][104]
    unsigned short* As = sm;
    unsigned short* Bs = sm + 128*104;
    int mt = blockIdx.x, nt = blockIdx.y, eb = blockIdx.z;
    int tb = eb & 31;
    int tid = threadIdx.x, lane = tid & 31, warp = tid >> 5;

    const uint4* gq = (const uint4*)(g_qb + ((long)eb*256 + nt*128)*96);
    for (int idx = tid; idx < 1536; idx += 256) {
        int i = idx / 12, s = idx % 12;
        *(uint4*)(As + i*104 + s*8) = gq[idx];
    }
    const uint4* gk = (const uint4*)(g_kb + ((long)tb*256 + mt*128)*96);
    for (int idx = tid; idx < 1536; idx += 256) {
        int i = idx / 12, s = idx % 12;
        *(uint4*)(Bs + i*104 + s*8) = gk[idx];
    }
    __syncthreads();

    int wn = (warp >> 2) * 64, wm = (warp & 3) * 32;
    float acc[4][4][4] = {};
    uint32_t base = smem_u32(sm);
    int aRow = lane & 15, aK = (lane >> 4) * 8;
    int bRow = lane & 7,  bK = ((lane >> 3) & 1) * 8;

    #pragma unroll
    for (int kt = 0; kt < 6; kt++) {
        uint32_t a[4][4], bf[4][2];
        #pragma unroll
        for (int r = 0; r < 4; r++) {
            uint32_t ad = base + (uint32_t)(((wn + r*16 + aRow)*104 + kt*16 + aK) * 2);
            LDMX4(a[r][0], a[r][1], a[r][2], a[r][3], ad);
        }
        #pragma unroll
        for (int c = 0; c < 4; c++) {
            uint32_t ad = base + (uint32_t)((128*104 + (wm + c*8 + bRow)*104 + kt*16 + bK) * 2);
            LDMX2(bf[c][0], bf[c][1], ad);
        }
        #pragma unroll
        for (int r = 0; r < 4; r++)
            #pragma unroll
            for (int c = 0; c < 4; c++)
                MMA16816(acc[r][c][0], acc[r][c][1], acc[r][c][2], acc[r][c][3],
                         a[r][0], a[r][1], a[r][2], a[r][3], bf[c][0], bf[c][1]);
    }

    unsigned short* ga = g_ab + (long)eb * 65536;
    #pragma unroll
    for (int r = 0; r < 4; r++) {
        int n = nt*128 + wn + r*16 + (lane >> 2);
        #pragma unroll
        for (int c = 0; c < 4; c++) {
            int m = mt*128 + wm + c*8 + (lane & 3)*2;
            uint32_t p0 = (uint32_t)__bfloat16_as_ushort(__float2bfloat16(acc[r][c][0]))
                        | ((uint32_t)__bfloat16_as_ushort(__float2bfloat16(acc[r][c][1])) << 16);
            uint32_t p1 = (uint32_t)__bfloat16_as_ushort(__float2bfloat16(acc[r][c][2]))
                        | ((uint32_t)__bfloat16_as_ushort(__float2bfloat16(acc[r][c][3])) << 16);
            *(uint32_t*)(ga + (long)n*256 + m)       = p0;
            *(uint32_t*)(ga + (long)(n+8)*256 + m)   = p1;
        }
    }
}

// ================= res via mma.sync ========================================
__global__ __launch_bounds__(256) void res_mma_kernel()
{
    __shared__ unsigned short As[128*72];
    __shared__ unsigned short Bs[128*72];
    int dt = blockIdx.x, nt = blockIdx.y, eb = blockIdx.z;
    int tb = eb & 31;
    int tid = threadIdx.x, lane = tid & 31, warp = tid >> 5;
    int wn = (warp >> 2) * 64, wm = (warp & 3) * 32;
    float acc[4][4][4] = {};
    uint32_t baseA = smem_u32(As), baseB = smem_u32(Bs);
    int aRow = lane & 15, aK = (lane >> 4) * 8;
    int bRow = lane & 7,  bK = ((lane >> 3) & 1) * 8;

    for (int ch = 0; ch < 4; ch++) {
        const uint4* gA = (const uint4*)(g_ab + ((long)eb*256 + nt*128)*256 + ch*64);
        for (int idx = tid; idx < 1024; idx += 256) {
            int i = idx >> 3, s = idx & 7;
            *(uint4*)(As + i*72 + s*8) = gA[i*32 + s];
        }
        const uint4* gB = (const uint4*)(g_vb + ((long)tb*384 + dt*128)*256 + ch*64);
        for (int idx = tid; idx < 1024; idx += 256) {
            int i = idx >> 3, s = idx & 7;
            *(uint4*)(Bs + i*72 + s*8) = gB[i*32 + s];
        }
        __syncthreads();
        #pragma unroll
        for (int kt = 0; kt < 4; kt++) {
            uint32_t a[4][4], bf[4][2];
            #pragma unroll
            for (int r = 0; r < 4; r++) {
                uint32_t ad = baseA + (uint32_t)(((wn + r*16 + aRow)*72 + kt*16 + aK) * 2);
                LDMX4(a[r][0], a[r][1], a[r][2], a[r][3], ad);
            }
            #pragma unroll
            for (int c = 0; c < 4; c++) {
                uint32_t ad = baseB + (uint32_t)(((wm + c*8 + bRow)*72 + kt*16 + bK) * 2);
                LDMX2(bf[c][0], bf[c][1], ad);
            }
            #pragma unroll
            for (int r = 0; r < 4; r++)
                #pragma unroll
                for (int c = 0; c < 4; c++)
                    MMA16816(acc[r][c][0], acc[r][c][1], acc[r][c][2], acc[r][c][3],
                             a[r][0], a[r][1], a[r][2], a[r][3], bf[c][0], bf[c][1]);
        }
        __syncthreads();
    }

    #pragma unroll
    for (int r = 0; r < 4; r++) {
        int n = nt*128 + wn + r*16 + (lane >> 2);
        #pragma unroll
        for (int c = 0; c < 4; c++) {
            int d = dt*128 + wm + c*8 + (lane & 3)*2;
            float2 v0 = make_float2(acc[r][c][0], acc[r][c][1]);
            float2 v1 = make_float2(acc[r][c][2], acc[r][c][3]);
            *(float2*)(g_res + ((long)eb*256 + n)*384 + d)     = v0;
            *(float2*)(g_res + ((long)eb*256 + n + 8)*384 + d) = v1;
        }
    }
}

// ========== exact-fp32 linear via 3-split bf16 mma =========================
__global__ __launch_bounds__(256) void wmma_lin_kernel(
    const unsigned short* __restrict__ A3, const unsigned short* __restrict__ Bb,
    float* __restrict__ outF,
    const float* __restrict__ bias, const float* __restrict__ scale,
    const float* __restrict__ shift, int M, int K)
{
    __shared__ unsigned short As[3*128*40];
    __shared__ unsigned short Bs[128*40];
    int mt = blockIdx.x, nt = blockIdx.y, z = blockIdx.z;
    int tid = threadIdx.x, lane = tid & 31, warp = tid >> 5;
    int m0 = mt * 128;
    int wn = (warp >> 2) * 64, wm = (warp & 3) * 32;
    float acc[4][4][4] = {};
    uint32_t baseA = smem_u32(As), baseB = smem_u32(Bs);
    int aRow = lane & 15, aK = (lane >> 4) * 8;
    int bRow = lane & 7,  bK = ((lane >> 3) & 1) * 8;

    for (int k0 = 0; k0 < K; k0 += 32) {
        for (int idx = tid; idx < 1536; idx += 256) {
            int s = idx / 512, r = idx % 512;
            int i = r >> 2, p4 = r & 3;
            *(uint4*)(As + (s*128 + i)*40 + p4*8) =
                *(const uint4*)(A3 + ((long)s*M + m0 + i)*K + k0 + p4*8);
        }
        for (int idx = tid; idx < 512; idx += 256) {
            int i = idx >> 2, p4 = idx & 3;
            *(uint4*)(Bs + i*40 + p4*8) =
                *(const uint4*)(Bb + ((long)z*256 + nt*128 + i)*K + k0 + p4*8);
        }
        __syncthreads();
        #pragma unroll
        for (int kt = 0; kt < 2; kt++) {
            uint32_t bf[4][2];
            #pragma unroll
            for (int c = 0; c < 4; c++) {
                uint32_t ad = baseB + (uint32_t)(((wm + c*8 + bRow)*40 + kt*16 + bK) * 2);
                LDMX2(bf[c][0], bf[c][1], ad);
            }
            #pragma unroll
            for (int s = 0; s < 3; s++) {
                uint32_t a[4][4];
                #pragma unroll
                for (int r = 0; r < 4; r++) {
                    uint32_t ad = baseA + (uint32_t)(((s*128 + wn + r*16 + aRow)*40 + kt*16 + aK) * 2);
                    LDMX4(a[r][0], a[r][1], a[r][2], a[r][3], ad);
                }
                #pragma unroll
                for (int r = 0; r < 4; r++)
                    #pragma unroll
                    for (int c = 0; c < 4; c++)
                        MMA16816(acc[r][c][0], acc[r][c][1], acc[r][c][2], acc[r][c][3],
                                 a[r][0], a[r][1], a[r][2], a[r][3], bf[c][0], bf[c][1]);
            }
        }
        __syncthreads();
    }

    #pragma unroll
    for (int r = 0; r < 4; r++) {
        int m  = m0 + wn + r*16 + (lane >> 2);
        float bi0 = bias[m],   sc0 = scale[m]   * BNS, sh0 = shift[m];
        float bi1 = bias[m+8], sc1 = scale[m+8] * BNS, sh1 = shift[m+8];
        #pragma unroll
        for (int c = 0; c < 4; c++) {
            int n = nt*128 + wm + c*8 + (lane & 3)*2;
            float2 v0, v1;
            v0.x = (acc[r][c][0] + bi0) * sc0 + sh0;
            v0.y = (acc[r][c][1] + bi0) * sc0 + sh0;
            v1.x = (acc[r][c][2] + bi1) * sc1 + sh1;
            v1.y = (acc[r][c][3] + bi1) * sc1 + sh1;
            *(float2*)(outF + ((long)z*M + m)*256 + n)     = v0;
            *(float2*)(outF + ((long)z*M + m + 8)*256 + n) = v1;
        }
    }
}

// ================= helper kernels ==========================================
__global__ void wsplit3_kernel(const float* __restrict__ w, unsigned short* __restrict__ w3, int total)
{
    int i = blockIdx.x * 256 + threadIdx.x;
    if (i >= total) return;
    float x = w[i];
    __nv_bfloat16 h0 = __float2bfloat16(x);
    float r1 = x - __bfloat162float(h0);
    __nv_bfloat16 h1 = __float2bfloat16(r1);
    float r2 = r1 - __bfloat162float(h1);
    __nv_bfloat16 h2 = __float2bfloat16(r2);
    w3[i]             = __bfloat16_as_ushort(h0);
    w3[total + i]     = __bfloat16_as_ushort(h1);
    w3[2 * total + i] = __bfloat16_as_ushort(h2);
}

// fused res-LIF + router combine: reads res PRE-acts, emits bf16 y (exact ints)
__global__ void combine_lif_kernel()
{
    long tid = (long)blockIdx.x * 256 + threadIdx.x;
    if (tid >= (long)8 * 256 * 384) return;
    int d = (int)(tid % 384);
    int n = (int)((tid / 384) % 256);
    int b = (int)(tid / (384 * 256));
    float y[4] = {0.f, 0.f, 0.f, 0.f};
    #pragma unroll
    for (int e = 0; e < 4; e++) {
        float mem = 0.f;
        #pragma unroll
        for (int t = 0; t < 4; t++) {
            int eb = e * 32 + t * 8 + b;
            float pre = g_res[((long)eb * 256 + n) * 384 + d];
            mem = mem + (pre - mem) * 0.5f;
            float sp = (mem >= 1.f) ? 1.f : 0.f;
            mem *= (1.f - sp);
            y[t] = fmaf(g_w[((t * 8 + b) * 4 + e) * 256 + n], sp, y[t]);
        }
    }
    #pragma unroll
    for (int t = 0; t < 4; t++)
        g_yb[((long)(t * 8 + b) * 256 + n) * 384 + d] =
            __bfloat16_as_ushort(__float2bfloat16(y[t]));
}

__global__ void transpose_m_kernel()
{
    __shared__ unsigned short tile[32][33];
    int c0 = blockIdx.x * 32, n0 = blockIdx.y * 32, tb = blockIdx.z;
    int tx = threadIdx.x & 31, ty = threadIdx.x >> 5;
    #pragma unroll
    for (int p = 0; p < 4; p++) {
        int c = c0 + ty + p*8;
        tile[ty + p*8][tx] = __bfloat16_as_ushort(
            __float2bfloat16(g_m[((long)tb*1024 + c)*256 + n0 + tx]));
    }
    __syncthreads();
    #pragma unroll
    for (int p = 0; p < 4; p++) {
        int n = n0 + ty + p*8;
        g_mb[((long)tb*256 + n)*1024 + c0 + tx] = tile[tx][ty + p*8];
    }
}

__global__ void add_kernel(const float* __restrict__ a, const float* __restrict__ b,
                           float* __restrict__ o, int n)
{
    int i = blockIdx.x * 256 + threadIdx.x;
    if (i < n) o[i] = a[i] + b[i];
}

__global__ void dwconv_gate_kernel(const float* __restrict__ dw_w, const float* __restrict__ dw_b,
                                   const float* __restrict__ dw_g, const float* __restrict__ dw_be)
{
    int tid = blockIdx.x * 256 + threadIdx.x;
    if (tid >= 8 * 1024 * 256) return;
    int n  = tid & 255;
    int c  = (tid >> 8) & 1023;
    int b  = tid >> 18;
    int hh = n >> 4, ww = n & 15;
    float wk[9];
    #pragma unroll
    for (int i = 0; i < 9; i++) wk[i] = dw_w[c * 9 + i];
    float bi = dw_b[c], sc = dw_g[c] * BNS, sh = dw_be[c];
    float mem = 0.f;
    #pragma unroll
    for (int t = 0; t < 4; t++) {
        int tb = t * 8 + b;
        const float* x1 = g_h + ((long)tb * 2048 + c) * 256;
        float acc = bi;
        #pragma unroll
        for (int di = 0; di < 3; di++) {
            int yy = hh + di - 1;
            if (yy < 0 || yy > 15) continue;
            #pragma unroll
            for (int dj = 0; dj < 3; dj++) {
                int xx = ww + dj - 1;
                if (xx < 0 || xx > 15) continue;
                acc = fmaf(wk[di * 3 + dj], x1[yy * 16 + xx], acc);
            }
        }
        float pre = acc * sc + sh;
        mem = mem + (pre - mem) * 0.5f;
        float sp = (mem >= 1.f) ? 1.f : 0.f;
        mem *= (1.f - sp);
        float x2 = g_h[((long)tb * 2048 + 1024 + c) * 256 + n];
        g_m[((long)tb * 1024 + c) * 256 + n] = sp * x2;
    }
}

// ===========================================================================
extern "C" void kernel_launch(void* const* d_in, const int* in_sizes, int n_in,
                              void* d_out, int out_size)
{
    const float* x         = (const float*)d_in[0];
    const float* k_w       = (const float*)d_in[2];
    const float* v_w       = (const float*)d_in[3];
    const float* router_w  = (const float*)d_in[4];
    const float* router_b  = (const float*)d_in[5];
    const float* router_g  = (const float*)d_in[6];
    const float* router_be = (const float*)d_in[7];
    const float* exp_w     = (const float*)d_in[8];
    const float* exp_g     = (const float*)d_in[9];
    const float* exp_b     = (const float*)d_in[10];
    const float* proj_w    = (const float*)d_in[11];
    const float* proj_b    = (const float*)d_in[12];
    const float* proj_g    = (const float*)d_in[13];
    const float* proj_be   = (const float*)d_in[14];
    const float* fc1_w     = (const float*)d_in[15];
    const float* fc1_b     = (const float*)d_in[16];
    const float* fc1_g     = (const float*)d_in[17];
    const float* fc1_be    = (const float*)d_in[18];
    const float* dw_w      = (const float*)d_in[19];
    const float* dw_b      = (const float*)d_in[20];
    const float* dw_g      = (const float*)d_in[21];
    const float* dw_be     = (const float*)d_in[22];
    const float* fc2_w     = (const float*)d_in[23];
    const float* fc2_b     = (const float*)d_in[24];
    const float* fc2_g     = (const float*)d_in[25];
    const float* fc2_be    = (const float*)d_in[26];
    float* out = (float*)d_out;

    float *pk, *pv, *pw, *pq, *pp, *pxr, *ph, *pm, *pf2, *pres;
    unsigned short *pqb, *pkb, *pvb, *pyb, *pmb, *pw3a, *pw3b;
    cudaGetSymbolAddress((void**)&pk,   g_k);
    cudaGetSymbolAddress((void**)&pv,   g_v);
    cudaGetSymbolAddress((void**)&pw,   g_w);
    cudaGetSymbolAddress((void**)&pq,   g_q);
    cudaGetSymbolAddress((void**)&pres, g_res);
    cudaGetSymbolAddress((void**)&pp,   g_p);
    cudaGetSymbolAddress((void**)&pxr,  g_xr);
    cudaGetSymbolAddress((void**)&ph,   g_h);
    cudaGetSymbolAddress((void**)&pm,   g_m);
    cudaGetSymbolAddress((void**)&pf2,  g_f2);
    cudaGetSymbolAddress((void**)&pqb,  g_qb);
    cudaGetSymbolAddress((void**)&pkb,  g_kb);
    cudaGetSymbolAddress((void**)&pvb,  g_vb);
    cudaGetSymbolAddress((void**)&pyb,  g_yb);
    cudaGetSymbolAddress((void**)&pmb,  g_mb);
    cudaGetSymbolAddress((void**)&pw3a, g_w3a);
    cudaGetSymbolAddress((void**)&pw3b, g_w3b);

    cudaFuncSetAttribute(attn_mma_kernel, cudaFuncAttributeMaxDynamicSharedMemorySize, 53248);

    const long XB = 384 * 256;
    dim3 blk(256);

    // weight splits
    wsplit3_kernel<<<(384*384+255)/256,blk>>>(proj_w, pw3a, 384*384);
    wsplit3_kernel<<<(384*1024+255)/256,blk>>>(fc2_w, pw3b, 384*1024);

    // --- SSA pre-activations ---
    gemm_kernel<true,false><<<dim3(4,2,32),blk>>>(k_w,0,0,384,1, x,0,XB,256,1,
        pk, nullptr,nullptr,nullptr,0, 96,256,384,32);
    gemm_kernel<true,false><<<dim3(4,6,32),blk>>>(v_w,0,0,384,1, x,0,XB,256,1,
        pv, nullptr,nullptr,nullptr,0, 384,256,384,32);
    gemm_kernel<true,false><<<dim3(4,1,32),blk>>>(router_w,0,0,384,1, x,0,XB,256,1,
        pw, router_b,router_g,router_be,0, 4,256,384,32);
    // q: z2 kernel (2 slabs share exp_w tile)
    gemm_z2_kernel<<<dim3(4,2,64),blk>>>(exp_w,(long)96*384, x,XB,
        pq, nullptr,exp_g,exp_b,96, 96,384);

    // --- LIF -> bf16 spikes in mma layouts ---
    lif_k_kernel<<<(8*96*256+255)/256,blk>>>();
    lif_v_kernel<<<(8*384*256+255)/256,blk>>>();
    lif4_kernel<<<(8*256+255)/256,blk>>>((float4*)pw, 1, 0, 256);
    lif_q_kernel<<<(4*8*96*256+255)/256,blk>>>();

    // --- tensor-core attention ---
    attn_mma_kernel<<<dim3(2,2,128),blk,53248>>>();
    res_mma_kernel<<<dim3(3,2,128),blk>>>();

    // fused res-LIF + combine -> bf16 y
    combine_lif_kernel<<<(8*256*384+255)/256,blk>>>();

    // proj on tensor cores -> fp32 pre-acts -> LIF
    wmma_lin_kernel<<<dim3(3,2,32),blk>>>(pw3a, pyb, pp, proj_b, proj_g, proj_be, 384, 384);
    lif4_kernel<<<(8*24576+255)/256,blk>>>((float4*)pp, 1, 0, 24576);
    add_kernel<<<(32*384*256+255)/256,blk>>>(x, pp, pxr, 32*384*256);

    // --- MLP ---
    // fc1: z2 kernel (2 slabs share fc1_w tile)
    gemm_z2_kernel<<<dim3(4,32,16),blk>>>(fc1_w,0, pxr,XB,
        ph, fc1_b,fc1_g,fc1_be,0, 2048,384);
    lif4_kernel<<<(8*131072+255)/256,blk>>>((float4*)ph, 1, 0, 131072);
    dwconv_gate_kernel<<<(8*1024*256+255)/256,blk>>>(dw_w, dw_b, dw_g, dw_be);
    transpose_m_kernel<<<dim3(32,8,32),blk>>>();

    // fc2 on tensor cores -> fp32 pre-acts -> LIF
    wmma_lin_kernel<<<dim3(3,2,32),blk>>>(pw3b, pmb, pf2, fc2_b, fc2_g, fc2_be, 384, 1024);
    lif4_kernel<<<(8*24576+255)/256,blk>>>((float4*)pf2, 1, 0, 24576);

    add_kernel<<<(32*384*256+255)/256,blk>>>(pxr, pf2, out, 32*384*256);
}

// round 9
// speedup vs baseline: 1.1840x; 1.0372x over previous
#include <cuda_runtime.h>
#include <cuda_bf16.h>
#include <cstdint>
#include <math.h>

#define BNS 0.9999950000374996f  // 1/sqrt(1+1e-5)

// ================= scratch (device globals) ================================
__device__ float g_k   [32*96*256];
__device__ float g_v   [32*384*256];
__device__ float g_w   [32*4*256];
__device__ float g_q   [4*32*96*256];
__device__ float g_res [4*32*256*384];     // res PRE-acts (E*TB,N,C)
__device__ float g_p   [32*384*256];       // proj PRE-acts
__device__ float g_xr  [32*384*256];
__device__ float g_h   [32*2048*256];
__device__ float g_m   [32*1024*256];
__device__ float g_f2  [32*384*256];       // fc2 PRE-acts
__device__ unsigned short g_qb[128*256*96];
__device__ unsigned short g_kb[32*256*96];
__device__ unsigned short g_vb[32*384*256];
__device__ unsigned short g_ab[128*256*256];
__device__ unsigned short g_yb[32*256*384];
__device__ unsigned short g_mb[32*256*1024];
__device__ unsigned short g_w3a[3*384*384];
__device__ unsigned short g_w3b[3*384*1024];

__device__ __forceinline__ uint32_t smem_u32(const void* p){
    uint32_t a;
    asm("{ .reg .u64 t; cvta.to.shared.u64 t, %1; cvt.u32.u64 %0, t; }" : "=r"(a) : "l"(p));
    return a;
}
#define LDMX4(r0,r1,r2,r3,ad) \
    asm volatile("ldmatrix.sync.aligned.m8n8.x4.shared.b16 {%0,%1,%2,%3}, [%4];" \
        : "=r"(r0),"=r"(r1),"=r"(r2),"=r"(r3) : "r"(ad))
#define LDMX2(r0,r1,ad) \
    asm volatile("ldmatrix.sync.aligned.m8n8.x2.shared.b16 {%0,%1}, [%2];" \
        : "=r"(r0),"=r"(r1) : "r"(ad))
#define MMA16816(c0,c1,c2,c3,a0,a1,a2,a3,b0,b1) \
    asm volatile("mma.sync.aligned.m16n8k16.row.col.f32.bf16.bf16.f32 " \
        "{%0,%1,%2,%3}, {%4,%5,%6,%7}, {%8,%9}, {%0,%1,%2,%3};" \
        : "+f"(c0),"+f"(c1),"+f"(c2),"+f"(c3) \
        : "r"(a0),"r"(a1),"r"(a2),"r"(a3),"r"(b0),"r"(b1))

// ============ SIMT GEMM, 2 z-slabs sharing one A tile, vector loads ========
// N fixed 256, B row-major [k][256] (n contiguous), A [M][K] k-contiguous.
// slabs: slab0 = g*32 + p, slab1 = slab0 + 16 (p = bz & 15, g = bz >> 4)
__global__ __launch_bounds__(256) void gemm_z2_kernel(
    const float* __restrict__ A, long aG,
    const float* __restrict__ B, long bSlab,
    float* __restrict__ C,
    const float* __restrict__ bias, const float* __restrict__ scale,
    const float* __restrict__ shift, int pG,
    int M, int K)
{
    __shared__ float As[16][68];
    __shared__ float Bs[2][16][68];
    int bz = blockIdx.z;
    int g = bz >> 4, p = bz & 15;
    const float* Ap = A + (long)g * aG;
    const float* Bp0 = B + (long)p * bSlab;
    const float* Bp1 = B + (long)(p + 16) * bSlab;
    int m0 = blockIdx.y * 64, n0 = blockIdx.x * 64;
    int tid = threadIdx.x, tx = tid & 15, ty = tid >> 4;
    float acc[2][4][4] = {};

    int am = tid >> 2, ak = (tid & 3) * 4;
    int bk = tid >> 4, bn = (tid & 15) * 4;

    for (int k0 = 0; k0 < K; k0 += 16) {
        float4 a4 = make_float4(0.f, 0.f, 0.f, 0.f);
        if (m0 + am < M) a4 = *(const float4*)&Ap[(long)(m0 + am) * K + k0 + ak];
        long boff = (long)(k0 + bk) * 256 + n0 + bn;
        float4 v0 = *(const float4*)&Bp0[boff];
        float4 v1 = *(const float4*)&Bp1[boff];
        As[ak + 0][am] = a4.x;
        As[ak + 1][am] = a4.y;
        As[ak + 2][am] = a4.z;
        As[ak + 3][am] = a4.w;
        *(float4*)&Bs[0][bk][bn] = v0;
        *(float4*)&Bs[1][bk][bn] = v1;
        __syncthreads();
        #pragma unroll
        for (int kk = 0; kk < 16; kk++) {
            float4 av4 = *(const float4*)&As[kk][ty * 4];
            float av[4] = {av4.x, av4.y, av4.z, av4.w};
            #pragma unroll
            for (int s = 0; s < 2; s++) {
                float4 bv4 = *(const float4*)&Bs[s][kk][tx * 4];
                float bv[4] = {bv4.x, bv4.y, bv4.z, bv4.w};
                #pragma unroll
                for (int u = 0; u < 4; u++)
                    #pragma unroll
                    for (int v = 0; v < 4; v++)
                        acc[s][u][v] = fmaf(av[u], bv[v], acc[s][u][v]);
            }
        }
        __syncthreads();
    }

    #pragma unroll
    for (int s = 0; s < 2; s++) {
        long slab = (long)g * 32 + p + s * 16;
        #pragma unroll
        for (int u = 0; u < 4; u++) {
            int m = m0 + ty * 4 + u;
            if (m >= M) continue;
            float bi = bias  ? bias [g * pG + m]       : 0.f;
            float sc = scale ? scale[g * pG + m] * BNS : 1.f;
            float sh = shift ? shift[g * pG + m]       : 0.f;
            float4 o;
            o.x = (acc[s][u][0] + bi) * sc + sh;
            o.y = (acc[s][u][1] + bi) * sc + sh;
            o.z = (acc[s][u][2] + bi) * sc + sh;
            o.w = (acc[s][u][3] + bi) * sc + sh;
            *(float4*)&C[slab * M * 256 + (long)m * 256 + n0 + tx * 4] = o;
        }
    }
}

// ================= LIF kernels =============================================
__global__ void lif4_kernel(float4* __restrict__ buf, long M4)
{
    long tid = (long)blockIdx.x * blockDim.x + threadIdx.x;
    long total = 8 * M4;
    if (tid >= total) return;
    long j = tid % M4;
    int  b = (int)(tid / M4);
    float4 mem = make_float4(0.f, 0.f, 0.f, 0.f);
    #pragma unroll
    for (int t = 0; t < 4; t++) {
        long idx = (long)(t * 8 + b) * M4 + j;
        float4 x = buf[idx];
        float4 sp;
        mem.x += (x.x - mem.x) * 0.5f; sp.x = (mem.x >= 1.f) ? 1.f : 0.f; mem.x *= (1.f - sp.x);
        mem.y += (x.y - mem.y) * 0.5f; sp.y = (mem.y >= 1.f) ? 1.f : 0.f; mem.y *= (1.f - sp.y);
        mem.z += (x.z - mem.z) * 0.5f; sp.z = (mem.z >= 1.f) ? 1.f : 0.f; mem.z *= (1.f - sp.z);
        mem.w += (x.w - mem.w) * 0.5f; sp.w = (mem.w >= 1.f) ? 1.f : 0.f; mem.w *= (1.f - sp.w);
        buf[idx] = sp;
    }
}

// LIF + add base: outv = base + spike(pre)
__global__ void lif4_add_kernel(const float4* __restrict__ pre, const float4* __restrict__ base,
                                float4* __restrict__ outv, long M4)
{
    long tid = (long)blockIdx.x * blockDim.x + threadIdx.x;
    long total = 8 * M4;
    if (tid >= total) return;
    long j = tid % M4;
    int  b = (int)(tid / M4);
    float4 mem = make_float4(0.f, 0.f, 0.f, 0.f);
    #pragma unroll
    for (int t = 0; t < 4; t++) {
        long idx = (long)(t * 8 + b) * M4 + j;
        float4 x = pre[idx];
        float4 bs = base[idx];
        float4 sp;
        mem.x += (x.x - mem.x) * 0.5f; sp.x = (mem.x >= 1.f) ? 1.f : 0.f; mem.x *= (1.f - sp.x);
        mem.y += (x.y - mem.y) * 0.5f; sp.y = (mem.y >= 1.f) ? 1.f : 0.f; mem.y *= (1.f - sp.y);
        mem.z += (x.z - mem.z) * 0.5f; sp.z = (mem.z >= 1.f) ? 1.f : 0.f; mem.z *= (1.f - sp.z);
        mem.w += (x.w - mem.w) * 0.5f; sp.w = (mem.w >= 1.f) ? 1.f : 0.f; mem.w *= (1.f - sp.w);
        outv[idx] = make_float4(bs.x + sp.x, bs.y + sp.y, bs.z + sp.z, bs.w + sp.w);
    }
}

__global__ void lif_q_kernel()
{
    int tid = blockIdx.x * 256 + threadIdx.x;
    if (tid >= 4*8*96*256) return;
    int n = tid & 255;
    int c = (tid >> 8) % 96;
    int b = (tid / (256*96)) & 7;
    int e = tid / (256*96*8);
    float mem = 0.f;
    #pragma unroll
    for (int t = 0; t < 4; t++) {
        int eb = e*32 + t*8 + b;
        float x = g_q[((long)eb*96 + c)*256 + n];
        mem = mem + (x - mem) * 0.5f;
        unsigned short sp = (mem >= 1.f) ? 0x3F80 : 0;
        mem *= (sp ? 0.f : 1.f);
        g_qb[((long)eb*256 + n)*96 + c] = sp;
    }
}
__global__ void lif_k_kernel()
{
    int tid = blockIdx.x * 256 + threadIdx.x;
    if (tid >= 8*96*256) return;
    int m = tid & 255;
    int c = (tid >> 8) % 96;
    int b = tid / (256*96);
    float mem = 0.f;
    #pragma unroll
    for (int t = 0; t < 4; t++) {
        int tb = t*8 + b;
        float x = g_k[((long)tb*96 + c)*256 + m];
        mem = mem + (x - mem) * 0.5f;
        unsigned short sp = (mem >= 1.f) ? 0x3F80 : 0;
        mem *= (sp ? 0.f : 1.f);
        g_kb[((long)tb*256 + m)*96 + c] = sp;
    }
}
__global__ void lif_v_kernel()
{
    int tid = blockIdx.x * 256 + threadIdx.x;
    if (tid >= 8*384*256) return;
    int m = tid & 255;
    int d = (tid >> 8) % 384;
    int b = tid / (256*384);
    float mem = 0.f;
    #pragma unroll
    for (int t = 0; t < 4; t++) {
        int tb = t*8 + b;
        long idx = ((long)tb*384 + d)*256 + m;
        float x = g_v[idx];
        mem = mem + (x - mem) * 0.5f;
        unsigned short sp = (mem >= 1.f) ? 0x3F80 : 0;
        mem *= (sp ? 0.f : 1.f);
        g_vb[idx] = sp;
    }
}

// ================= attn via mma.sync =======================================
__global__ __launch_bounds__(256) void attn_mma_kernel()
{
    extern __shared__ unsigned short sm[];    // As[128][104], Bs[128][104]
    unsigned short* As = sm;
    unsigned short* Bs = sm + 128*104;
    int mt = blockIdx.x, nt = blockIdx.y, eb = blockIdx.z;
    int tb = eb & 31;
    int tid = threadIdx.x, lane = tid & 31, warp = tid >> 5;

    const uint4* gq = (const uint4*)(g_qb + ((long)eb*256 + nt*128)*96);
    for (int idx = tid; idx < 1536; idx += 256) {
        int i = idx / 12, s = idx % 12;
        *(uint4*)(As + i*104 + s*8) = gq[idx];
    }
    const uint4* gk = (const uint4*)(g_kb + ((long)tb*256 + mt*128)*96);
    for (int idx = tid; idx < 1536; idx += 256) {
        int i = idx / 12, s = idx % 12;
        *(uint4*)(Bs + i*104 + s*8) = gk[idx];
    }
    __syncthreads();

    int wn = (warp >> 2) * 64, wm = (warp & 3) * 32;
    float acc[4][4][4] = {};
    uint32_t base = smem_u32(sm);
    int aRow = lane & 15, aK = (lane >> 4) * 8;
    int bRow = lane & 7,  bK = ((lane >> 3) & 1) * 8;

    #pragma unroll
    for (int kt = 0; kt < 6; kt++) {
        uint32_t a[4][4], bf[4][2];
        #pragma unroll
        for (int r = 0; r < 4; r++) {
            uint32_t ad = base + (uint32_t)(((wn + r*16 + aRow)*104 + kt*16 + aK) * 2);
            LDMX4(a[r][0], a[r][1], a[r][2], a[r][3], ad);
        }
        #pragma unroll
        for (int c = 0; c < 4; c++) {
            uint32_t ad = base + (uint32_t)((128*104 + (wm + c*8 + bRow)*104 + kt*16 + bK) * 2);
            LDMX2(bf[c][0], bf[c][1], ad);
        }
        #pragma unroll
        for (int r = 0; r < 4; r++)
            #pragma unroll
            for (int c = 0; c < 4; c++)
                MMA16816(acc[r][c][0], acc[r][c][1], acc[r][c][2], acc[r][c][3],
                         a[r][0], a[r][1], a[r][2], a[r][3], bf[c][0], bf[c][1]);
    }

    unsigned short* ga = g_ab + (long)eb * 65536;
    #pragma unroll
    for (int r = 0; r < 4; r++) {
        int n = nt*128 + wn + r*16 + (lane >> 2);
        #pragma unroll
        for (int c = 0; c < 4; c++) {
            int m = mt*128 + wm + c*8 + (lane & 3)*2;
            uint32_t p0 = (uint32_t)__bfloat16_as_ushort(__float2bfloat16(acc[r][c][0]))
                        | ((uint32_t)__bfloat16_as_ushort(__float2bfloat16(acc[r][c][1])) << 16);
            uint32_t p1 = (uint32_t)__bfloat16_as_ushort(__float2bfloat16(acc[r][c][2]))
                        | ((uint32_t)__bfloat16_as_ushort(__float2bfloat16(acc[r][c][3])) << 16);
            *(uint32_t*)(ga + (long)n*256 + m)       = p0;
            *(uint32_t*)(ga + (long)(n+8)*256 + m)   = p1;
        }
    }
}

// ================= res via mma.sync ========================================
__global__ __launch_bounds__(256) void res_mma_kernel()
{
    __shared__ unsigned short As[128*72];
    __shared__ unsigned short Bs[128*72];
    int dt = blockIdx.x, nt = blockIdx.y, eb = blockIdx.z;
    int tb = eb & 31;
    int tid = threadIdx.x, lane = tid & 31, warp = tid >> 5;
    int wn = (warp >> 2) * 64, wm = (warp & 3) * 32;
    float acc[4][4][4] = {};
    uint32_t baseA = smem_u32(As), baseB = smem_u32(Bs);
    int aRow = lane & 15, aK = (lane >> 4) * 8;
    int bRow = lane & 7,  bK = ((lane >> 3) & 1) * 8;

    for (int ch = 0; ch < 4; ch++) {
        const uint4* gA = (const uint4*)(g_ab + ((long)eb*256 + nt*128)*256 + ch*64);
        for (int idx = tid; idx < 1024; idx += 256) {
            int i = idx >> 3, s = idx & 7;
            *(uint4*)(As + i*72 + s*8) = gA[i*32 + s];
        }
        const uint4* gB = (const uint4*)(g_vb + ((long)tb*384 + dt*128)*256 + ch*64);
        for (int idx = tid; idx < 1024; idx += 256) {
            int i = idx >> 3, s = idx & 7;
            *(uint4*)(Bs + i*72 + s*8) = gB[i*32 + s];
        }
        __syncthreads();
        #pragma unroll
        for (int kt = 0; kt < 4; kt++) {
            uint32_t a[4][4], bf[4][2];
            #pragma unroll
            for (int r = 0; r < 4; r++) {
                uint32_t ad = baseA + (uint32_t)(((wn + r*16 + aRow)*72 + kt*16 + aK) * 2);
                LDMX4(a[r][0], a[r][1], a[r][2], a[r][3], ad);
            }
            #pragma unroll
            for (int c = 0; c < 4; c++) {
                uint32_t ad = baseB + (uint32_t)(((wm + c*8 + bRow)*72 + kt*16 + bK) * 2);
                LDMX2(bf[c][0], bf[c][1], ad);
            }
            #pragma unroll
            for (int r = 0; r < 4; r++)
                #pragma unroll
                for (int c = 0; c < 4; c++)
                    MMA16816(acc[r][c][0], acc[r][c][1], acc[r][c][2], acc[r][c][3],
                             a[r][0], a[r][1], a[r][2], a[r][3], bf[c][0], bf[c][1]);
        }
        __syncthreads();
    }

    #pragma unroll
    for (int r = 0; r < 4; r++) {
        int n = nt*128 + wn + r*16 + (lane >> 2);
        #pragma unroll
        for (int c = 0; c < 4; c++) {
            int d = dt*128 + wm + c*8 + (lane & 3)*2;
            float2 v0 = make_float2(acc[r][c][0], acc[r][c][1]);
            float2 v1 = make_float2(acc[r][c][2], acc[r][c][3]);
            *(float2*)(g_res + ((long)eb*256 + n)*384 + d)     = v0;
            *(float2*)(g_res + ((long)eb*256 + n + 8)*384 + d) = v1;
        }
    }
}

// ========== exact-fp32 linear via 3-split bf16 mma =========================
__global__ __launch_bounds__(256) void wmma_lin_kernel(
    const unsigned short* __restrict__ A3, const unsigned short* __restrict__ Bb,
    float* __restrict__ outF,
    const float* __restrict__ bias, const float* __restrict__ scale,
    const float* __restrict__ shift, int M, int K)
{
    __shared__ unsigned short As[3*128*40];
    __shared__ unsigned short Bs[128*40];
    int mt = blockIdx.x, nt = blockIdx.y, z = blockIdx.z;
    int tid = threadIdx.x, lane = tid & 31, warp = tid >> 5;
    int m0 = mt * 128;
    int wn = (warp >> 2) * 64, wm = (warp & 3) * 32;
    float acc[4][4][4] = {};
    uint32_t baseA = smem_u32(As), baseB = smem_u32(Bs);
    int aRow = lane & 15, aK = (lane >> 4) * 8;
    int bRow = lane & 7,  bK = ((lane >> 3) & 1) * 8;

    for (int k0 = 0; k0 < K; k0 += 32) {
        for (int idx = tid; idx < 1536; idx += 256) {
            int s = idx / 512, r = idx % 512;
            int i = r >> 2, p4 = r & 3;
            *(uint4*)(As + (s*128 + i)*40 + p4*8) =
                *(const uint4*)(A3 + ((long)s*M + m0 + i)*K + k0 + p4*8);
        }
        for (int idx = tid; idx < 512; idx += 256) {
            int i = idx >> 2, p4 = idx & 3;
            *(uint4*)(Bs + i*40 + p4*8) =
                *(const uint4*)(Bb + ((long)z*256 + nt*128 + i)*K + k0 + p4*8);
        }
        __syncthreads();
        #pragma unroll
        for (int kt = 0; kt < 2; kt++) {
            uint32_t bf[4][2];
            #pragma unroll
            for (int c = 0; c < 4; c++) {
                uint32_t ad = baseB + (uint32_t)(((wm + c*8 + bRow)*40 + kt*16 + bK) * 2);
                LDMX2(bf[c][0], bf[c][1], ad);
            }
            #pragma unroll
            for (int s = 0; s < 3; s++) {
                uint32_t a[4][4];
                #pragma unroll
                for (int r = 0; r < 4; r++) {
                    uint32_t ad = baseA + (uint32_t)(((s*128 + wn + r*16 + aRow)*40 + kt*16 + aK) * 2);
                    LDMX4(a[r][0], a[r][1], a[r][2], a[r][3], ad);
                }
                #pragma unroll
                for (int r = 0; r < 4; r++)
                    #pragma unroll
                    for (int c = 0; c < 4; c++)
                        MMA16816(acc[r][c][0], acc[r][c][1], acc[r][c][2], acc[r][c][3],
                                 a[r][0], a[r][1], a[r][2], a[r][3], bf[c][0], bf[c][1]);
            }
        }
        __syncthreads();
    }

    #pragma unroll
    for (int r = 0; r < 4; r++) {
        int m  = m0 + wn + r*16 + (lane >> 2);
        float bi0 = bias[m],   sc0 = scale[m]   * BNS, sh0 = shift[m];
        float bi1 = bias[m+8], sc1 = scale[m+8] * BNS, sh1 = shift[m+8];
        #pragma unroll
        for (int c = 0; c < 4; c++) {
            int n = nt*128 + wm + c*8 + (lane & 3)*2;
            float2 v0, v1;
            v0.x = (acc[r][c][0] + bi0) * sc0 + sh0;
            v0.y = (acc[r][c][1] + bi0) * sc0 + sh0;
            v1.x = (acc[r][c][2] + bi1) * sc1 + sh1;
            v1.y = (acc[r][c][3] + bi1) * sc1 + sh1;
            *(float2*)(outF + ((long)z*M + m)*256 + n)     = v0;
            *(float2*)(outF + ((long)z*M + m + 8)*256 + n) = v1;
        }
    }
}

// ================= helper kernels ==========================================
__global__ void wsplit3_kernel(const float* __restrict__ w, unsigned short* __restrict__ w3, int total)
{
    int i = blockIdx.x * 256 + threadIdx.x;
    if (i >= total) return;
    float x = w[i];
    __nv_bfloat16 h0 = __float2bfloat16(x);
    float r1 = x - __bfloat162float(h0);
    __nv_bfloat16 h1 = __float2bfloat16(r1);
    float r2 = r1 - __bfloat162float(h1);
    __nv_bfloat16 h2 = __float2bfloat16(r2);
    w3[i]             = __bfloat16_as_ushort(h0);
    w3[total + i]     = __bfloat16_as_ushort(h1);
    w3[2 * total + i] = __bfloat16_as_ushort(h2);
}

// fused res-LIF + router combine: reads res PRE-acts, emits bf16 y (exact ints)
__global__ void combine_lif_kernel()
{
    long tid = (long)blockIdx.x * 256 + threadIdx.x;
    if (tid >= (long)8 * 256 * 384) return;
    int d = (int)(tid % 384);
    int n = (int)((tid / 384) % 256);
    int b = (int)(tid / (384 * 256));
    float y[4] = {0.f, 0.f, 0.f, 0.f};
    #pragma unroll
    for (int e = 0; e < 4; e++) {
        float mem = 0.f;
        #pragma unroll
        for (int t = 0; t < 4; t++) {
            int eb = e * 32 + t * 8 + b;
            float pre = g_res[((long)eb * 256 + n) * 384 + d];
            mem = mem + (pre - mem) * 0.5f;
            float sp = (mem >= 1.f) ? 1.f : 0.f;
            mem *= (1.f - sp);
            y[t] = fmaf(g_w[((t * 8 + b) * 4 + e) * 256 + n], sp, y[t]);
        }
    }
    #pragma unroll
    for (int t = 0; t < 4; t++)
        g_yb[((long)(t * 8 + b) * 256 + n) * 384 + d] =
            __bfloat16_as_ushort(__float2bfloat16(y[t]));
}

__global__ void transpose_m_kernel()
{
    __shared__ unsigned short tile[32][33];
    int c0 = blockIdx.x * 32, n0 = blockIdx.y * 32, tb = blockIdx.z;
    int tx = threadIdx.x & 31, ty = threadIdx.x >> 5;
    #pragma unroll
    for (int p = 0; p < 4; p++) {
        int c = c0 + ty + p*8;
        tile[ty + p*8][tx] = __bfloat16_as_ushort(
            __float2bfloat16(g_m[((long)tb*1024 + c)*256 + n0 + tx]));
    }
    __syncthreads();
    #pragma unroll
    for (int p = 0; p < 4; p++) {
        int n = n0 + ty + p*8;
        g_mb[((long)tb*256 + n)*1024 + c0 + tx] = tile[tx][ty + p*8];
    }
}

__global__ void dwconv_gate_kernel(const float* __restrict__ dw_w, const float* __restrict__ dw_b,
                                   const float* __restrict__ dw_g, const float* __restrict__ dw_be)
{
    int tid = blockIdx.x * 256 + threadIdx.x;
    if (tid >= 8 * 1024 * 256) return;
    int n  = tid & 255;
    int c  = (tid >> 8) & 1023;
    int b  = tid >> 18;
    int hh = n >> 4, ww = n & 15;
    float wk[9];
    #pragma unroll
    for (int i = 0; i < 9; i++) wk[i] = dw_w[c * 9 + i];
    float bi = dw_b[c], sc = dw_g[c] * BNS, sh = dw_be[c];
    float mem = 0.f;
    #pragma unroll
    for (int t = 0; t < 4; t++) {
        int tb = t * 8 + b;
        const float* x1 = g_h + ((long)tb * 2048 + c) * 256;
        float acc = bi;
        #pragma unroll
        for (int di = 0; di < 3; di++) {
            int yy = hh + di - 1;
            if (yy < 0 || yy > 15) continue;
            #pragma unroll
            for (int dj = 0; dj < 3; dj++) {
                int xx = ww + dj - 1;
                if (xx < 0 || xx > 15) continue;
                acc = fmaf(wk[di * 3 + dj], x1[yy * 16 + xx], acc);
            }
        }
        float pre = acc * sc + sh;
        mem = mem + (pre - mem) * 0.5f;
        float sp = (mem >= 1.f) ? 1.f : 0.f;
        mem *= (1.f - sp);
        float x2 = g_h[((long)tb * 2048 + 1024 + c) * 256 + n];
        g_m[((long)tb * 1024 + c) * 256 + n] = sp * x2;
    }
}

// ===========================================================================
extern "C" void kernel_launch(void* const* d_in, const int* in_sizes, int n_in,
                              void* d_out, int out_size)
{
    const float* x         = (const float*)d_in[0];
    const float* k_w       = (const float*)d_in[2];
    const float* v_w       = (const float*)d_in[3];
    const float* router_w  = (const float*)d_in[4];
    const float* router_b  = (const float*)d_in[5];
    const float* router_g  = (const float*)d_in[6];
    const float* router_be = (const float*)d_in[7];
    const float* exp_w     = (const float*)d_in[8];
    const float* exp_g     = (const float*)d_in[9];
    const float* exp_b     = (const float*)d_in[10];
    const float* proj_w    = (const float*)d_in[11];
    const float* proj_b    = (const float*)d_in[12];
    const float* proj_g    = (const float*)d_in[13];
    const float* proj_be   = (const float*)d_in[14];
    const float* fc1_w     = (const float*)d_in[15];
    const float* fc1_b     = (const float*)d_in[16];
    const float* fc1_g     = (const float*)d_in[17];
    const float* fc1_be    = (const float*)d_in[18];
    const float* dw_w      = (const float*)d_in[19];
    const float* dw_b      = (const float*)d_in[20];
    const float* dw_g      = (const float*)d_in[21];
    const float* dw_be     = (const float*)d_in[22];
    const float* fc2_w     = (const float*)d_in[23];
    const float* fc2_b     = (const float*)d_in[24];
    const float* fc2_g     = (const float*)d_in[25];
    const float* fc2_be    = (const float*)d_in[26];
    float* out = (float*)d_out;

    float *pk, *pv, *pw, *pq, *pp, *pxr, *ph, *pm, *pf2, *pres;
    unsigned short *pqb, *pkb, *pvb, *pyb, *pmb, *pw3a, *pw3b;
    cudaGetSymbolAddress((void**)&pk,   g_k);
    cudaGetSymbolAddress((void**)&pv,   g_v);
    cudaGetSymbolAddress((void**)&pw,   g_w);
    cudaGetSymbolAddress((void**)&pq,   g_q);
    cudaGetSymbolAddress((void**)&pres, g_res);
    cudaGetSymbolAddress((void**)&pp,   g_p);
    cudaGetSymbolAddress((void**)&pxr,  g_xr);
    cudaGetSymbolAddress((void**)&ph,   g_h);
    cudaGetSymbolAddress((void**)&pm,   g_m);
    cudaGetSymbolAddress((void**)&pf2,  g_f2);
    cudaGetSymbolAddress((void**)&pqb,  g_qb);
    cudaGetSymbolAddress((void**)&pkb,  g_kb);
    cudaGetSymbolAddress((void**)&pvb,  g_vb);
    cudaGetSymbolAddress((void**)&pyb,  g_yb);
    cudaGetSymbolAddress((void**)&pmb,  g_mb);
    cudaGetSymbolAddress((void**)&pw3a, g_w3a);
    cudaGetSymbolAddress((void**)&pw3b, g_w3b);

    cudaFuncSetAttribute(attn_mma_kernel, cudaFuncAttributeMaxDynamicSharedMemorySize, 53248);

    const long XB = 384 * 256;
    dim3 blk(256);

    // weight splits
    wsplit3_kernel<<<(384*384+255)/256,blk>>>(proj_w, pw3a, 384*384);
    wsplit3_kernel<<<(384*1024+255)/256,blk>>>(fc2_w, pw3b, 384*1024);

    // --- SSA pre-activations: all via z2 (A tile shared across 2 slabs) ---
    gemm_z2_kernel<<<dim3(4,2,16),blk>>>(k_w,0, x,XB,
        pk, nullptr,nullptr,nullptr,0, 96,384);
    gemm_z2_kernel<<<dim3(4,6,16),blk>>>(v_w,0, x,XB,
        pv, nullptr,nullptr,nullptr,0, 384,384);
    gemm_z2_kernel<<<dim3(4,1,16),blk>>>(router_w,0, x,XB,
        pw, router_b,router_g,router_be,0, 4,384);
    gemm_z2_kernel<<<dim3(4,2,64),blk>>>(exp_w,(long)96*384, x,XB,
        pq, nullptr,exp_g,exp_b,96, 96,384);

    // --- LIF -> bf16 spikes in mma layouts ---
    lif_k_kernel<<<(8*96*256+255)/256,blk>>>();
    lif_v_kernel<<<(8*384*256+255)/256,blk>>>();
    lif4_kernel<<<(8*256+255)/256,blk>>>((float4*)pw, 256);
    lif_q_kernel<<<(4*8*96*256+255)/256,blk>>>();

    // --- tensor-core attention ---
    attn_mma_kernel<<<dim3(2,2,128),blk,53248>>>();
    res_mma_kernel<<<dim3(3,2,128),blk>>>();

    // fused res-LIF + combine -> bf16 y
    combine_lif_kernel<<<(8*256*384+255)/256,blk>>>();

    // proj on tensor cores -> pre-acts; fused LIF+residual: xr = x + spike(p)
    wmma_lin_kernel<<<dim3(3,2,32),blk>>>(pw3a, pyb, pp, proj_b, proj_g, proj_be, 384, 384);
    lif4_add_kernel<<<(8*24576+255)/256,blk>>>((const float4*)pp, (const float4*)x,
                                               (float4*)pxr, 24576);

    // --- MLP ---
    gemm_z2_kernel<<<dim3(4,32,16),blk>>>(fc1_w,0, pxr,XB,
        ph, fc1_b,fc1_g,fc1_be,0, 2048,384);
    lif4_kernel<<<(8*131072+255)/256,blk>>>((float4*)ph, 131072);
    dwconv_gate_kernel<<<(8*1024*256+255)/256,blk>>>(dw_w, dw_b, dw_g, dw_be);
    transpose_m_kernel<<<dim3(32,8,32),blk>>>();

    // fc2 on tensor cores -> pre-acts; fused LIF+residual: out = xr + spike(f2)
    wmma_lin_kernel<<<dim3(3,2,32),blk>>>(pw3b, pmb, pf2, fc2_b, fc2_g, fc2_be, 384, 1024);
    lif4_add_kernel<<<(8*24576+255)/256,blk>>>((const float4*)pf2, (const float4*)pxr,
                                               (float4*)out, 24576);
}

// round 10
// speedup vs baseline: 1.1976x; 1.0115x over previous
#include <cuda_runtime.h>
#include <cuda_bf16.h>
#include <cstdint>
#include <math.h>

#define BNS 0.9999950000374996f  // 1/sqrt(1+1e-5)

// ================= scratch (device globals) ================================
__device__ float g_k   [32*96*256];
__device__ float g_v   [32*384*256];
__device__ float g_w   [32*4*256];
__device__ float g_q   [4*32*96*256];
__device__ float g_res [4*32*256*384];     // res PRE-acts (E*TB,N,C)
__device__ float g_p   [32*384*256];       // proj PRE-acts
__device__ float g_xr  [32*384*256];
__device__ float g_h   [32*2048*256];
__device__ float g_m   [32*1024*256];
__device__ float g_f2  [32*384*256];       // fc2 PRE-acts
__device__ unsigned short g_qb[128*256*96];
__device__ unsigned short g_kb[32*256*96];
__device__ unsigned short g_vb[32*384*256];
__device__ unsigned short g_ab[128*256*256];
__device__ unsigned short g_yb[32*256*384];
__device__ unsigned short g_mb[32*256*1024];
__device__ unsigned short g_w3a[3*384*384];
__device__ unsigned short g_w3b[3*384*1024];

__device__ __forceinline__ uint32_t smem_u32(const void* p){
    uint32_t a;
    asm("{ .reg .u64 t; cvta.to.shared.u64 t, %1; cvt.u32.u64 %0, t; }" : "=r"(a) : "l"(p));
    return a;
}
#define LDMX4(r0,r1,r2,r3,ad) \
    asm volatile("ldmatrix.sync.aligned.m8n8.x4.shared.b16 {%0,%1,%2,%3}, [%4];" \
        : "=r"(r0),"=r"(r1),"=r"(r2),"=r"(r3) : "r"(ad))
#define LDMX2(r0,r1,ad) \
    asm volatile("ldmatrix.sync.aligned.m8n8.x2.shared.b16 {%0,%1}, [%2];" \
        : "=r"(r0),"=r"(r1) : "r"(ad))
#define MMA16816(c0,c1,c2,c3,a0,a1,a2,a3,b0,b1) \
    asm volatile("mma.sync.aligned.m16n8k16.row.col.f32.bf16.bf16.f32 " \
        "{%0,%1,%2,%3}, {%4,%5,%6,%7}, {%8,%9}, {%0,%1,%2,%3};" \
        : "+f"(c0),"+f"(c1),"+f"(c2),"+f"(c3) \
        : "r"(a0),"r"(a1),"r"(a2),"r"(a3),"r"(b0),"r"(b1))

// ============ SIMT GEMM, 2 z-slabs sharing one A tile ======================
// slabs: slab0 = g*32 + p, slab1 = slab0 + 16 (p = bz & 15, g = bz >> 4)
__global__ __launch_bounds__(256) void gemm_z2_kernel(
    const float* __restrict__ A, long aG,
    const float* __restrict__ B, long bSlab,
    float* __restrict__ C,
    const float* __restrict__ bias, const float* __restrict__ scale,
    const float* __restrict__ shift, int pG,
    int M, int K)
{
    __shared__ float As[16][68];
    __shared__ float Bs[2][16][68];
    int bz = blockIdx.z;
    int g = bz >> 4, p = bz & 15;
    const float* Ap = A + (long)g * aG;
    const float* Bp0 = B + (long)p * bSlab;
    const float* Bp1 = B + (long)(p + 16) * bSlab;
    int m0 = blockIdx.y * 64, n0 = blockIdx.x * 64;
    int tid = threadIdx.x, tx = tid & 15, ty = tid >> 4;
    float acc[2][4][4] = {};

    int am = tid >> 2, ak = (tid & 3) * 4;
    int bk = tid >> 4, bn = (tid & 15) * 4;

    for (int k0 = 0; k0 < K; k0 += 16) {
        float4 a4 = make_float4(0.f, 0.f, 0.f, 0.f);
        if (m0 + am < M) a4 = *(const float4*)&Ap[(long)(m0 + am) * K + k0 + ak];
        long boff = (long)(k0 + bk) * 256 + n0 + bn;
        float4 v0 = *(const float4*)&Bp0[boff];
        float4 v1 = *(const float4*)&Bp1[boff];
        As[ak + 0][am] = a4.x;
        As[ak + 1][am] = a4.y;
        As[ak + 2][am] = a4.z;
        As[ak + 3][am] = a4.w;
        *(float4*)&Bs[0][bk][bn] = v0;
        *(float4*)&Bs[1][bk][bn] = v1;
        __syncthreads();
        #pragma unroll
        for (int kk = 0; kk < 16; kk++) {
            float4 av4 = *(const float4*)&As[kk][ty * 4];
            float av[4] = {av4.x, av4.y, av4.z, av4.w};
            #pragma unroll
            for (int s = 0; s < 2; s++) {
                float4 bv4 = *(const float4*)&Bs[s][kk][tx * 4];
                float bv[4] = {bv4.x, bv4.y, bv4.z, bv4.w};
                #pragma unroll
                for (int u = 0; u < 4; u++)
                    #pragma unroll
                    for (int v = 0; v < 4; v++)
                        acc[s][u][v] = fmaf(av[u], bv[v], acc[s][u][v]);
            }
        }
        __syncthreads();
    }

    #pragma unroll
    for (int s = 0; s < 2; s++) {
        long slab = (long)g * 32 + p + s * 16;
        #pragma unroll
        for (int u = 0; u < 4; u++) {
            int m = m0 + ty * 4 + u;
            if (m >= M) continue;
            float bi = bias  ? bias [g * pG + m]       : 0.f;
            float sc = scale ? scale[g * pG + m] * BNS : 1.f;
            float sh = shift ? shift[g * pG + m]       : 0.f;
            float4 o;
            o.x = (acc[s][u][0] + bi) * sc + sh;
            o.y = (acc[s][u][1] + bi) * sc + sh;
            o.z = (acc[s][u][2] + bi) * sc + sh;
            o.w = (acc[s][u][3] + bi) * sc + sh;
            *(float4*)&C[slab * M * 256 + (long)m * 256 + n0 + tx * 4] = o;
        }
    }
}

// ============ SIMT GEMM, 4 z-slabs sharing one A tile ======================
// slabs: g*32 + p + 8*s, s=0..3 (p = bz & 7, g = bz >> 3)
__global__ __launch_bounds__(256) void gemm_z4_kernel(
    const float* __restrict__ A, long aG,
    const float* __restrict__ B, long bSlab,
    float* __restrict__ C,
    const float* __restrict__ bias, const float* __restrict__ scale,
    const float* __restrict__ shift, int pG,
    int M, int K)
{
    __shared__ float As[16][68];
    __shared__ float Bs[4][16][68];
    int bz = blockIdx.z;
    int g = bz >> 3, p = bz & 7;
    const float* Ap = A + (long)g * aG;
    int m0 = blockIdx.y * 64, n0 = blockIdx.x * 64;
    int tid = threadIdx.x, tx = tid & 15, ty = tid >> 4;
    float acc[4][4][4] = {};

    int am = tid >> 2, ak = (tid & 3) * 4;
    int bk = tid >> 4, bn = (tid & 15) * 4;
    const float* Bp[4];
    #pragma unroll
    for (int s = 0; s < 4; s++) Bp[s] = B + (long)(p + 8 * s) * bSlab;

    for (int k0 = 0; k0 < K; k0 += 16) {
        float4 a4 = make_float4(0.f, 0.f, 0.f, 0.f);
        if (m0 + am < M) a4 = *(const float4*)&Ap[(long)(m0 + am) * K + k0 + ak];
        long boff = (long)(k0 + bk) * 256 + n0 + bn;
        float4 bv4[4];
        #pragma unroll
        for (int s = 0; s < 4; s++) bv4[s] = *(const float4*)&Bp[s][boff];
        As[ak + 0][am] = a4.x;
        As[ak + 1][am] = a4.y;
        As[ak + 2][am] = a4.z;
        As[ak + 3][am] = a4.w;
        #pragma unroll
        for (int s = 0; s < 4; s++) *(float4*)&Bs[s][bk][bn] = bv4[s];
        __syncthreads();
        #pragma unroll
        for (int kk = 0; kk < 16; kk++) {
            float4 av4 = *(const float4*)&As[kk][ty * 4];
            float av[4] = {av4.x, av4.y, av4.z, av4.w};
            #pragma unroll
            for (int s = 0; s < 4; s++) {
                float4 b4 = *(const float4*)&Bs[s][kk][tx * 4];
                float bv[4] = {b4.x, b4.y, b4.z, b4.w};
                #pragma unroll
                for (int u = 0; u < 4; u++)
                    #pragma unroll
                    for (int v = 0; v < 4; v++)
                        acc[s][u][v] = fmaf(av[u], bv[v], acc[s][u][v]);
            }
        }
        __syncthreads();
    }

    #pragma unroll
    for (int s = 0; s < 4; s++) {
        long slab = (long)g * 32 + p + 8 * s;
        #pragma unroll
        for (int u = 0; u < 4; u++) {
            int m = m0 + ty * 4 + u;
            if (m >= M) continue;
            float bi = bias  ? bias [g * pG + m]       : 0.f;
            float sc = scale ? scale[g * pG + m] * BNS : 1.f;
            float sh = shift ? shift[g * pG + m]       : 0.f;
            float4 o;
            o.x = (acc[s][u][0] + bi) * sc + sh;
            o.y = (acc[s][u][1] + bi) * sc + sh;
            o.z = (acc[s][u][2] + bi) * sc + sh;
            o.w = (acc[s][u][3] + bi) * sc + sh;
            *(float4*)&C[slab * M * 256 + (long)m * 256 + n0 + tx * 4] = o;
        }
    }
}

// ================= LIF kernels =============================================
__global__ void lif4_kernel(float4* __restrict__ buf, long M4)
{
    long tid = (long)blockIdx.x * blockDim.x + threadIdx.x;
    long total = 8 * M4;
    if (tid >= total) return;
    long j = tid % M4;
    int  b = (int)(tid / M4);
    float4 mem = make_float4(0.f, 0.f, 0.f, 0.f);
    #pragma unroll
    for (int t = 0; t < 4; t++) {
        long idx = (long)(t * 8 + b) * M4 + j;
        float4 x = buf[idx];
        float4 sp;
        mem.x += (x.x - mem.x) * 0.5f; sp.x = (mem.x >= 1.f) ? 1.f : 0.f; mem.x *= (1.f - sp.x);
        mem.y += (x.y - mem.y) * 0.5f; sp.y = (mem.y >= 1.f) ? 1.f : 0.f; mem.y *= (1.f - sp.y);
        mem.z += (x.z - mem.z) * 0.5f; sp.z = (mem.z >= 1.f) ? 1.f : 0.f; mem.z *= (1.f - sp.z);
        mem.w += (x.w - mem.w) * 0.5f; sp.w = (mem.w >= 1.f) ? 1.f : 0.f; mem.w *= (1.f - sp.w);
        buf[idx] = sp;
    }
}

// LIF + add base: outv = base + spike(pre)
__global__ void lif4_add_kernel(const float4* __restrict__ pre, const float4* __restrict__ base,
                                float4* __restrict__ outv, long M4)
{
    long tid = (long)blockIdx.x * blockDim.x + threadIdx.x;
    long total = 8 * M4;
    if (tid >= total) return;
    long j = tid % M4;
    int  b = (int)(tid / M4);
    float4 mem = make_float4(0.f, 0.f, 0.f, 0.f);
    #pragma unroll
    for (int t = 0; t < 4; t++) {
        long idx = (long)(t * 8 + b) * M4 + j;
        float4 x = pre[idx];
        float4 bs = base[idx];
        float4 sp;
        mem.x += (x.x - mem.x) * 0.5f; sp.x = (mem.x >= 1.f) ? 1.f : 0.f; mem.x *= (1.f - sp.x);
        mem.y += (x.y - mem.y) * 0.5f; sp.y = (mem.y >= 1.f) ? 1.f : 0.f; mem.y *= (1.f - sp.y);
        mem.z += (x.z - mem.z) * 0.5f; sp.z = (mem.z >= 1.f) ? 1.f : 0.f; mem.z *= (1.f - sp.z);
        mem.w += (x.w - mem.w) * 0.5f; sp.w = (mem.w >= 1.f) ? 1.f : 0.f; mem.w *= (1.f - sp.w);
        outv[idx] = make_float4(bs.x + sp.x, bs.y + sp.y, bs.z + sp.z, bs.w + sp.w);
    }
}

__global__ void lif_q_kernel()
{
    int tid = blockIdx.x * 256 + threadIdx.x;
    if (tid >= 4*8*96*256) return;
    int n = tid & 255;
    int c = (tid >> 8) % 96;
    int b = (tid / (256*96)) & 7;
    int e = tid / (256*96*8);
    float mem = 0.f;
    #pragma unroll
    for (int t = 0; t < 4; t++) {
        int eb = e*32 + t*8 + b;
        float x = g_q[((long)eb*96 + c)*256 + n];
        mem = mem + (x - mem) * 0.5f;
        unsigned short sp = (mem >= 1.f) ? 0x3F80 : 0;
        mem *= (sp ? 0.f : 1.f);
        g_qb[((long)eb*256 + n)*96 + c] = sp;
    }
}
__global__ void lif_k_kernel()
{
    int tid = blockIdx.x * 256 + threadIdx.x;
    if (tid >= 8*96*256) return;
    int m = tid & 255;
    int c = (tid >> 8) % 96;
    int b = tid / (256*96);
    float mem = 0.f;
    #pragma unroll
    for (int t = 0; t < 4; t++) {
        int tb = t*8 + b;
        float x = g_k[((long)tb*96 + c)*256 + m];
        mem = mem + (x - mem) * 0.5f;
        unsigned short sp = (mem >= 1.f) ? 0x3F80 : 0;
        mem *= (sp ? 0.f : 1.f);
        g_kb[((long)tb*256 + m)*96 + c] = sp;
    }
}
__global__ void lif_v_kernel()
{
    int tid = blockIdx.x * 256 + threadIdx.x;
    if (tid >= 8*384*256) return;
    int m = tid & 255;
    int d = (tid >> 8) % 384;
    int b = tid / (256*384);
    float mem = 0.f;
    #pragma unroll
    for (int t = 0; t < 4; t++) {
        int tb = t*8 + b;
        long idx = ((long)tb*384 + d)*256 + m;
        float x = g_v[idx];
        mem = mem + (x - mem) * 0.5f;
        unsigned short sp = (mem >= 1.f) ? 0x3F80 : 0;
        mem *= (sp ? 0.f : 1.f);
        g_vb[idx] = sp;
    }
}

// ================= attn via mma.sync =======================================
__global__ __launch_bounds__(256) void attn_mma_kernel()
{
    extern __shared__ unsigned short sm[];    // As[128][104], Bs[128][104]
    unsigned short* As = sm;
    unsigned short* Bs = sm + 128*104;
    int mt = blockIdx.x, nt = blockIdx.y, eb = blockIdx.z;
    int tb = eb & 31;
    int tid = threadIdx.x, lane = tid & 31, warp = tid >> 5;

    const uint4* gq = (const uint4*)(g_qb + ((long)eb*256 + nt*128)*96);
    for (int idx = tid; idx < 1536; idx += 256) {
        int i = idx / 12, s = idx % 12;
        *(uint4*)(As + i*104 + s*8) = gq[idx];
    }
    const uint4* gk = (const uint4*)(g_kb + ((long)tb*256 + mt*128)*96);
    for (int idx = tid; idx < 1536; idx += 256) {
        int i = idx / 12, s = idx % 12;
        *(uint4*)(Bs + i*104 + s*8) = gk[idx];
    }
    __syncthreads();

    int wn = (warp >> 2) * 64, wm = (warp & 3) * 32;
    float acc[4][4][4] = {};
    uint32_t base = smem_u32(sm);
    int aRow = lane & 15, aK = (lane >> 4) * 8;
    int bRow = lane & 7,  bK = ((lane >> 3) & 1) * 8;

    #pragma unroll
    for (int kt = 0; kt < 6; kt++) {
        uint32_t a[4][4], bf[4][2];
        #pragma unroll
        for (int r = 0; r < 4; r++) {
            uint32_t ad = base + (uint32_t)(((wn + r*16 + aRow)*104 + kt*16 + aK) * 2);
            LDMX4(a[r][0], a[r][1], a[r][2], a[r][3], ad);
        }
        #pragma unroll
        for (int c = 0; c < 4; c++) {
            uint32_t ad = base + (uint32_t)((128*104 + (wm + c*8 + bRow)*104 + kt*16 + bK) * 2);
            LDMX2(bf[c][0], bf[c][1], ad);
        }
        #pragma unroll
        for (int r = 0; r < 4; r++)
            #pragma unroll
            for (int c = 0; c < 4; c++)
                MMA16816(acc[r][c][0], acc[r][c][1], acc[r][c][2], acc[r][c][3],
                         a[r][0], a[r][1], a[r][2], a[r][3], bf[c][0], bf[c][1]);
    }

    unsigned short* ga = g_ab + (long)eb * 65536;
    #pragma unroll
    for (int r = 0; r < 4; r++) {
        int n = nt*128 + wn + r*16 + (lane >> 2);
        #pragma unroll
        for (int c = 0; c < 4; c++) {
            int m = mt*128 + wm + c*8 + (lane & 3)*2;
            uint32_t p0 = (uint32_t)__bfloat16_as_ushort(__float2bfloat16(acc[r][c][0]))
                        | ((uint32_t)__bfloat16_as_ushort(__float2bfloat16(acc[r][c][1])) << 16);
            uint32_t p1 = (uint32_t)__bfloat16_as_ushort(__float2bfloat16(acc[r][c][2]))
                        | ((uint32_t)__bfloat16_as_ushort(__float2bfloat16(acc[r][c][3])) << 16);
            *(uint32_t*)(ga + (long)n*256 + m)       = p0;
            *(uint32_t*)(ga + (long)(n+8)*256 + m)   = p1;
        }
    }
}

// ================= res via mma.sync ========================================
__global__ __launch_bounds__(256) void res_mma_kernel()
{
    __shared__ unsigned short As[128*72];
    __shared__ unsigned short Bs[128*72];
    int dt = blockIdx.x, nt = blockIdx.y, eb = blockIdx.z;
    int tb = eb & 31;
    int tid = threadIdx.x, lane = tid & 31, warp = tid >> 5;
    int wn = (warp >> 2) * 64, wm = (warp & 3) * 32;
    float acc[4][4][4] = {};
    uint32_t baseA = smem_u32(As), baseB = smem_u32(Bs);
    int aRow = lane & 15, aK = (lane >> 4) * 8;
    int bRow = lane & 7,  bK = ((lane >> 3) & 1) * 8;

    for (int ch = 0; ch < 4; ch++) {
        const uint4* gA = (const uint4*)(g_ab + ((long)eb*256 + nt*128)*256 + ch*64);
        for (int idx = tid; idx < 1024; idx += 256) {
            int i = idx >> 3, s = idx & 7;
            *(uint4*)(As + i*72 + s*8) = gA[i*32 + s];
        }
        const uint4* gB = (const uint4*)(g_vb + ((long)tb*384 + dt*128)*256 + ch*64);
        for (int idx = tid; idx < 1024; idx += 256) {
            int i = idx >> 3, s = idx & 7;
            *(uint4*)(Bs + i*72 + s*8) = gB[i*32 + s];
        }
        __syncthreads();
        #pragma unroll
        for (int kt = 0; kt < 4; kt++) {
            uint32_t a[4][4], bf[4][2];
            #pragma unroll
            for (int r = 0; r < 4; r++) {
                uint32_t ad = baseA + (uint32_t)(((wn + r*16 + aRow)*72 + kt*16 + aK) * 2);
                LDMX4(a[r][0], a[r][1], a[r][2], a[r][3], ad);
            }
            #pragma unroll
            for (int c = 0; c < 4; c++) {
                uint32_t ad = baseB + (uint32_t)(((wm + c*8 + bRow)*72 + kt*16 + bK) * 2);
                LDMX2(bf[c][0], bf[c][1], ad);
            }
            #pragma unroll
            for (int r = 0; r < 4; r++)
                #pragma unroll
                for (int c = 0; c < 4; c++)
                    MMA16816(acc[r][c][0], acc[r][c][1], acc[r][c][2], acc[r][c][3],
                             a[r][0], a[r][1], a[r][2], a[r][3], bf[c][0], bf[c][1]);
        }
        __syncthreads();
    }

    #pragma unroll
    for (int r = 0; r < 4; r++) {
        int n = nt*128 + wn + r*16 + (lane >> 2);
        #pragma unroll
        for (int c = 0; c < 4; c++) {
            int d = dt*128 + wm + c*8 + (lane & 3)*2;
            float2 v0 = make_float2(acc[r][c][0], acc[r][c][1]);
            float2 v1 = make_float2(acc[r][c][2], acc[r][c][3]);
            *(float2*)(g_res + ((long)eb*256 + n)*384 + d)     = v0;
            *(float2*)(g_res + ((long)eb*256 + n + 8)*384 + d) = v1;
        }
    }
}

// ========== exact-fp32 linear via 3-split bf16 mma =========================
__global__ __launch_bounds__(256) void wmma_lin_kernel(
    const unsigned short* __restrict__ A3, const unsigned short* __restrict__ Bb,
    float* __restrict__ outF,
    const float* __restrict__ bias, const float* __restrict__ scale,
    const float* __restrict__ shift, int M, int K)
{
    __shared__ unsigned short As[3*128*40];
    __shared__ unsigned short Bs[128*40];
    int mt = blockIdx.x, nt = blockIdx.y, z = blockIdx.z;
    int tid = threadIdx.x, lane = tid & 31, warp = tid >> 5;
    int m0 = mt * 128;
    int wn = (warp >> 2) * 64, wm = (warp & 3) * 32;
    float acc[4][4][4] = {};
    uint32_t baseA = smem_u32(As), baseB = smem_u32(Bs);
    int aRow = lane & 15, aK = (lane >> 4) * 8;
    int bRow = lane & 7,  bK = ((lane >> 3) & 1) * 8;

    for (int k0 = 0; k0 < K; k0 += 32) {
        for (int idx = tid; idx < 1536; idx += 256) {
            int s = idx / 512, r = idx % 512;
            int i = r >> 2, p4 = r & 3;
            *(uint4*)(As + (s*128 + i)*40 + p4*8) =
                *(const uint4*)(A3 + ((long)s*M + m0 + i)*K + k0 + p4*8);
        }
        for (int idx = tid; idx < 512; idx += 256) {
            int i = idx >> 2, p4 = idx & 3;
            *(uint4*)(Bs + i*40 + p4*8) =
                *(const uint4*)(Bb + ((long)z*256 + nt*128 + i)*K + k0 + p4*8);
        }
        __syncthreads();
        #pragma unroll
        for (int kt = 0; kt < 2; kt++) {
            uint32_t bf[4][2];
            #pragma unroll
            for (int c = 0; c < 4; c++) {
                uint32_t ad = baseB + (uint32_t)(((wm + c*8 + bRow)*40 + kt*16 + bK) * 2);
                LDMX2(bf[c][0], bf[c][1], ad);
            }
            #pragma unroll
            for (int s = 0; s < 3; s++) {
                uint32_t a[4][4];
                #pragma unroll
                for (int r = 0; r < 4; r++) {
                    uint32_t ad = baseA + (uint32_t)(((s*128 + wn + r*16 + aRow)*40 + kt*16 + aK) * 2);
                    LDMX4(a[r][0], a[r][1], a[r][2], a[r][3], ad);
                }
                #pragma unroll
                for (int r = 0; r < 4; r++)
                    #pragma unroll
                    for (int c = 0; c < 4; c++)
                        MMA16816(acc[r][c][0], acc[r][c][1], acc[r][c][2], acc[r][c][3],
                                 a[r][0], a[r][1], a[r][2], a[r][3], bf[c][0], bf[c][1]);
            }
        }
        __syncthreads();
    }

    #pragma unroll
    for (int r = 0; r < 4; r++) {
        int m  = m0 + wn + r*16 + (lane >> 2);
        float bi0 = bias[m],   sc0 = scale[m]   * BNS, sh0 = shift[m];
        float bi1 = bias[m+8], sc1 = scale[m+8] * BNS, sh1 = shift[m+8];
        #pragma unroll
        for (int c = 0; c < 4; c++) {
            int n = nt*128 + wm + c*8 + (lane & 3)*2;
            float2 v0, v1;
            v0.x = (acc[r][c][0] + bi0) * sc0 + sh0;
            v0.y = (acc[r][c][1] + bi0) * sc0 + sh0;
            v1.x = (acc[r][c][2] + bi1) * sc1 + sh1;
            v1.y = (acc[r][c][3] + bi1) * sc1 + sh1;
            *(float2*)(outF + ((long)z*M + m)*256 + n)     = v0;
            *(float2*)(outF + ((long)z*M + m + 8)*256 + n) = v1;
        }
    }
}

// ================= helper kernels ==========================================
__global__ void wsplit3_kernel(const float* __restrict__ w, unsigned short* __restrict__ w3, int total)
{
    int i = blockIdx.x * 256 + threadIdx.x;
    if (i >= total) return;
    float x = w[i];
    __nv_bfloat16 h0 = __float2bfloat16(x);
    float r1 = x - __bfloat162float(h0);
    __nv_bfloat16 h1 = __float2bfloat16(r1);
    float r2 = r1 - __bfloat162float(h1);
    __nv_bfloat16 h2 = __float2bfloat16(r2);
    w3[i]             = __bfloat16_as_ushort(h0);
    w3[total + i]     = __bfloat16_as_ushort(h1);
    w3[2 * total + i] = __bfloat16_as_ushort(h2);
}

// fused res-LIF + router combine: reads res PRE-acts, emits bf16 y (exact ints)
__global__ void combine_lif_kernel()
{
    long tid = (long)blockIdx.x * 256 + threadIdx.x;
    if (tid >= (long)8 * 256 * 384) return;
    int d = (int)(tid % 384);
    int n = (int)((tid / 384) % 256);
    int b = (int)(tid / (384 * 256));
    float y[4] = {0.f, 0.f, 0.f, 0.f};
    #pragma unroll
    for (int e = 0; e < 4; e++) {
        float mem = 0.f;
        #pragma unroll
        for (int t = 0; t < 4; t++) {
            int eb = e * 32 + t * 8 + b;
            float pre = g_res[((long)eb * 256 + n) * 384 + d];
            mem = mem + (pre - mem) * 0.5f;
            float sp = (mem >= 1.f) ? 1.f : 0.f;
            mem *= (1.f - sp);
            y[t] = fmaf(g_w[((t * 8 + b) * 4 + e) * 256 + n], sp, y[t]);
        }
    }
    #pragma unroll
    for (int t = 0; t < 4; t++)
        g_yb[((long)(t * 8 + b) * 256 + n) * 384 + d] =
            __bfloat16_as_ushort(__float2bfloat16(y[t]));
}

__global__ void transpose_m_kernel()
{
    __shared__ unsigned short tile[32][33];
    int c0 = blockIdx.x * 32, n0 = blockIdx.y * 32, tb = blockIdx.z;
    int tx = threadIdx.x & 31, ty = threadIdx.x >> 5;
    #pragma unroll
    for (int p = 0; p < 4; p++) {
        int c = c0 + ty + p*8;
        tile[ty + p*8][tx] = __bfloat16_as_ushort(
            __float2bfloat16(g_m[((long)tb*1024 + c)*256 + n0 + tx]));
    }
    __syncthreads();
    #pragma unroll
    for (int p = 0; p < 4; p++) {
        int n = n0 + ty + p*8;
        g_mb[((long)tb*256 + n)*1024 + c0 + tx] = tile[tx][ty + p*8];
    }
}

__global__ void dwconv_gate_kernel(const float* __restrict__ dw_w, const float* __restrict__ dw_b,
                                   const float* __restrict__ dw_g, const float* __restrict__ dw_be)
{
    int tid = blockIdx.x * 256 + threadIdx.x;
    if (tid >= 8 * 1024 * 256) return;
    int n  = tid & 255;
    int c  = (tid >> 8) & 1023;
    int b  = tid >> 18;
    int hh = n >> 4, ww = n & 15;
    float wk[9];
    #pragma unroll
    for (int i = 0; i < 9; i++) wk[i] = dw_w[c * 9 + i];
    float bi = dw_b[c], sc = dw_g[c] * BNS, sh = dw_be[c];
    float mem = 0.f;
    #pragma unroll
    for (int t = 0; t < 4; t++) {
        int tb = t * 8 + b;
        const float* x1 = g_h + ((long)tb * 2048 + c) * 256;
        float acc = bi;
        #pragma unroll
        for (int di = 0; di < 3; di++) {
            int yy = hh + di - 1;
            if (yy < 0 || yy > 15) continue;
            #pragma unroll
            for (int dj = 0; dj < 3; dj++) {
                int xx = ww + dj - 1;
                if (xx < 0 || xx > 15) continue;
                acc = fmaf(wk[di * 3 + dj], x1[yy * 16 + xx], acc);
            }
        }
        float pre = acc * sc + sh;
        mem = mem + (pre - mem) * 0.5f;
        float sp = (mem >= 1.f) ? 1.f : 0.f;
        mem *= (1.f - sp);
        float x2 = g_h[((long)tb * 2048 + 1024 + c) * 256 + n];
        g_m[((long)tb * 1024 + c) * 256 + n] = sp * x2;
    }
}

// ===========================================================================
extern "C" void kernel_launch(void* const* d_in, const int* in_sizes, int n_in,
                              void* d_out, int out_size)
{
    const float* x         = (const float*)d_in[0];
    const float* k_w       = (const float*)d_in[2];
    const float* v_w       = (const float*)d_in[3];
    const float* router_w  = (const float*)d_in[4];
    const float* router_b  = (const float*)d_in[5];
    const float* router_g  = (const float*)d_in[6];
    const float* router_be = (const float*)d_in[7];
    const float* exp_w     = (const float*)d_in[8];
    const float* exp_g     = (const float*)d_in[9];
    const float* exp_b     = (const float*)d_in[10];
    const float* proj_w    = (const float*)d_in[11];
    const float* proj_b    = (const float*)d_in[12];
    const float* proj_g    = (const float*)d_in[13];
    const float* proj_be   = (const float*)d_in[14];
    const float* fc1_w     = (const float*)d_in[15];
    const float* fc1_b     = (const float*)d_in[16];
    const float* fc1_g     = (const float*)d_in[17];
    const float* fc1_be    = (const float*)d_in[18];
    const float* dw_w      = (const float*)d_in[19];
    const float* dw_b      = (const float*)d_in[20];
    const float* dw_g      = (const float*)d_in[21];
    const float* dw_be     = (const float*)d_in[22];
    const float* fc2_w     = (const float*)d_in[23];
    const float* fc2_b     = (const float*)d_in[24];
    const float* fc2_g     = (const float*)d_in[25];
    const float* fc2_be    = (const float*)d_in[26];
    float* out = (float*)d_out;

    float *pk, *pv, *pw, *pq, *pp, *pxr, *ph, *pm, *pf2, *pres;
    unsigned short *pqb, *pkb, *pvb, *pyb, *pmb, *pw3a, *pw3b;
    cudaGetSymbolAddress((void**)&pk,   g_k);
    cudaGetSymbolAddress((void**)&pv,   g_v);
    cudaGetSymbolAddress((void**)&pw,   g_w);
    cudaGetSymbolAddress((void**)&pq,   g_q);
    cudaGetSymbolAddress((void**)&pres, g_res);
    cudaGetSymbolAddress((void**)&pp,   g_p);
    cudaGetSymbolAddress((void**)&pxr,  g_xr);
    cudaGetSymbolAddress((void**)&ph,   g_h);
    cudaGetSymbolAddress((void**)&pm,   g_m);
    cudaGetSymbolAddress((void**)&pf2,  g_f2);
    cudaGetSymbolAddress((void**)&pqb,  g_qb);
    cudaGetSymbolAddress((void**)&pkb,  g_kb);
    cudaGetSymbolAddress((void**)&pvb,  g_vb);
    cudaGetSymbolAddress((void**)&pyb,  g_yb);
    cudaGetSymbolAddress((void**)&pmb,  g_mb);
    cudaGetSymbolAddress((void**)&pw3a, g_w3a);
    cudaGetSymbolAddress((void**)&pw3b, g_w3b);

    cudaFuncSetAttribute(attn_mma_kernel, cudaFuncAttributeMaxDynamicSharedMemorySize, 53248);

    const long XB = 384 * 256;
    dim3 blk(256);

    // weight splits
    wsplit3_kernel<<<(384*384+255)/256,blk>>>(proj_w, pw3a, 384*384);
    wsplit3_kernel<<<(384*1024+255)/256,blk>>>(fc2_w, pw3b, 384*1024);

    // --- SSA pre-activations ---
    gemm_z2_kernel<<<dim3(4,2,16),blk>>>(k_w,0, x,XB,
        pk, nullptr,nullptr,nullptr,0, 96,384);
    gemm_z4_kernel<<<dim3(4,6,8),blk>>>(v_w,0, x,XB,
        pv, nullptr,nullptr,nullptr,0, 384,384);
    gemm_z2_kernel<<<dim3(4,1,16),blk>>>(router_w,0, x,XB,
        pw, router_b,router_g,router_be,0, 4,384);
    gemm_z4_kernel<<<dim3(4,2,32),blk>>>(exp_w,(long)96*384, x,XB,
        pq, nullptr,exp_g,exp_b,96, 96,384);

    // --- LIF -> bf16 spikes in mma layouts ---
    lif_k_kernel<<<(8*96*256+255)/256,blk>>>();
    lif_v_kernel<<<(8*384*256+255)/256,blk>>>();
    lif4_kernel<<<(8*256+255)/256,blk>>>((float4*)pw, 256);
    lif_q_kernel<<<(4*8*96*256+255)/256,blk>>>();

    // --- tensor-core attention ---
    attn_mma_kernel<<<dim3(2,2,128),blk,53248>>>();
    res_mma_kernel<<<dim3(3,2,128),blk>>>();

    // fused res-LIF + combine -> bf16 y
    combine_lif_kernel<<<(8*256*384+255)/256,blk>>>();

    // proj on tensor cores -> pre-acts; fused LIF+residual: xr = x + spike(p)
    wmma_lin_kernel<<<dim3(3,2,32),blk>>>(pw3a, pyb, pp, proj_b, proj_g, proj_be, 384, 384);
    lif4_add_kernel<<<(8*24576+255)/256,blk>>>((const float4*)pp, (const float4*)x,
                                               (float4*)pxr, 24576);

    // --- MLP ---
    gemm_z4_kernel<<<dim3(4,32,8),blk>>>(fc1_w,0, pxr,XB,
        ph, fc1_b,fc1_g,fc1_be,0, 2048,384);
    lif4_kernel<<<(8*131072+255)/256,blk>>>((float4*)ph, 131072);
    dwconv_gate_kernel<<<(8*1024*256+255)/256,blk>>>(dw_w, dw_b, dw_g, dw_be);
    transpose_m_kernel<<<dim3(32,8,32),blk>>>();

    // fc2 on tensor cores -> pre-acts; fused LIF+residual: out = xr + spike(f2)
    wmma_lin_kernel<<<dim3(3,2,32),blk>>>(pw3b, pmb, pf2, fc2_b, fc2_g, fc2_be, 384, 1024);
    lif4_add_kernel<<<(8*24576+255)/256,blk>>>((const float4*)pf2, (const float4*)pxr,
                                               (float4*)out, 24576);
}

// round 11
// speedup vs baseline: 1.2160x; 1.0153x over previous
#include <cuda_runtime.h>
#include <cuda_bf16.h>
#include <cstdint>
#include <math.h>

#define BNS 0.9999950000374996f  // 1/sqrt(1+1e-5)

// ================= scratch (device globals) ================================
__device__ float g_k   [32*96*256];
__device__ float g_v   [32*384*256];
__device__ float g_w   [32*4*256];
__device__ float g_q   [4*32*96*256];
__device__ float g_res [4*32*256*384];     // res PRE-acts (E*TB,N,C)
__device__ float g_p   [32*384*256];       // proj PRE-acts
__device__ float g_xr  [32*384*256];
__device__ float g_h   [32*2048*256];
__device__ float g_m   [32*1024*256];
__device__ float g_f2  [32*384*256];       // fc2 PRE-acts
__device__ unsigned short g_qb[128*256*96];
__device__ unsigned short g_kb[32*256*96];
__device__ unsigned short g_vb[32*384*256];
__device__ unsigned short g_ab[128*256*256];
__device__ unsigned short g_yb[32*256*384];
__device__ unsigned short g_mb[32*256*1024];
__device__ unsigned short g_w3a[3*384*384];
__device__ unsigned short g_w3b[3*384*1024];

__device__ __forceinline__ uint32_t smem_u32(const void* p){
    uint32_t a;
    asm("{ .reg .u64 t; cvta.to.shared.u64 t, %1; cvt.u32.u64 %0, t; }" : "=r"(a) : "l"(p));
    return a;
}
#define LDMX4(r0,r1,r2,r3,ad) \
    asm volatile("ldmatrix.sync.aligned.m8n8.x4.shared.b16 {%0,%1,%2,%3}, [%4];" \
        : "=r"(r0),"=r"(r1),"=r"(r2),"=r"(r3) : "r"(ad))
#define LDMX2(r0,r1,ad) \
    asm volatile("ldmatrix.sync.aligned.m8n8.x2.shared.b16 {%0,%1}, [%2];" \
        : "=r"(r0),"=r"(r1) : "r"(ad))
#define MMA16816(c0,c1,c2,c3,a0,a1,a2,a3,b0,b1) \
    asm volatile("mma.sync.aligned.m16n8k16.row.col.f32.bf16.bf16.f32 " \
        "{%0,%1,%2,%3}, {%4,%5,%6,%7}, {%8,%9}, {%0,%1,%2,%3};" \
        : "+f"(c0),"+f"(c1),"+f"(c2),"+f"(c3) \
        : "r"(a0),"r"(a1),"r"(a2),"r"(a3),"r"(b0),"r"(b1))

// ============ SIMT GEMM, 2 z-slabs sharing one A tile ======================
__global__ __launch_bounds__(256) void gemm_z2_kernel(
    const float* __restrict__ A, long aG,
    const float* __restrict__ B, long bSlab,
    float* __restrict__ C,
    const float* __restrict__ bias, const float* __restrict__ scale,
    const float* __restrict__ shift, int pG,
    int M, int K)
{
    __shared__ float As[16][68];
    __shared__ float Bs[2][16][68];
    int bz = blockIdx.z;
    int g = bz >> 4, p = bz & 15;
    const float* Ap = A + (long)g * aG;
    const float* Bp0 = B + (long)p * bSlab;
    const float* Bp1 = B + (long)(p + 16) * bSlab;
    int m0 = blockIdx.y * 64, n0 = blockIdx.x * 64;
    int tid = threadIdx.x, tx = tid & 15, ty = tid >> 4;
    float acc[2][4][4] = {};

    int am = tid >> 2, ak = (tid & 3) * 4;
    int bk = tid >> 4, bn = (tid & 15) * 4;

    for (int k0 = 0; k0 < K; k0 += 16) {
        float4 a4 = make_float4(0.f, 0.f, 0.f, 0.f);
        if (m0 + am < M) a4 = *(const float4*)&Ap[(long)(m0 + am) * K + k0 + ak];
        long boff = (long)(k0 + bk) * 256 + n0 + bn;
        float4 v0 = *(const float4*)&Bp0[boff];
        float4 v1 = *(const float4*)&Bp1[boff];
        As[ak + 0][am] = a4.x;
        As[ak + 1][am] = a4.y;
        As[ak + 2][am] = a4.z;
        As[ak + 3][am] = a4.w;
        *(float4*)&Bs[0][bk][bn] = v0;
        *(float4*)&Bs[1][bk][bn] = v1;
        __syncthreads();
        #pragma unroll
        for (int kk = 0; kk < 16; kk++) {
            float4 av4 = *(const float4*)&As[kk][ty * 4];
            float av[4] = {av4.x, av4.y, av4.z, av4.w};
            #pragma unroll
            for (int s = 0; s < 2; s++) {
                float4 bv4 = *(const float4*)&Bs[s][kk][tx * 4];
                float bv[4] = {bv4.x, bv4.y, bv4.z, bv4.w};
                #pragma unroll
                for (int u = 0; u < 4; u++)
                    #pragma unroll
                    for (int v = 0; v < 4; v++)
                        acc[s][u][v] = fmaf(av[u], bv[v], acc[s][u][v]);
            }
        }
        __syncthreads();
    }

    #pragma unroll
    for (int s = 0; s < 2; s++) {
        long slab = (long)g * 32 + p + s * 16;
        #pragma unroll
        for (int u = 0; u < 4; u++) {
            int m = m0 + ty * 4 + u;
            if (m >= M) continue;
            float bi = bias  ? bias [g * pG + m]       : 0.f;
            float sc = scale ? scale[g * pG + m] * BNS : 1.f;
            float sh = shift ? shift[g * pG + m]       : 0.f;
            float4 o;
            o.x = (acc[s][u][0] + bi) * sc + sh;
            o.y = (acc[s][u][1] + bi) * sc + sh;
            o.z = (acc[s][u][2] + bi) * sc + sh;
            o.w = (acc[s][u][3] + bi) * sc + sh;
            *(float4*)&C[slab * M * 256 + (long)m * 256 + n0 + tx * 4] = o;
        }
    }
}

// ============ SIMT GEMM, 4 z-slabs sharing one A tile ======================
__global__ __launch_bounds__(256) void gemm_z4_kernel(
    const float* __restrict__ A, long aG,
    const float* __restrict__ B, long bSlab,
    float* __restrict__ C,
    const float* __restrict__ bias, const float* __restrict__ scale,
    const float* __restrict__ shift, int pG,
    int M, int K)
{
    __shared__ float As[16][68];
    __shared__ float Bs[4][16][68];
    int bz = blockIdx.z;
    int g = bz >> 3, p = bz & 7;
    const float* Ap = A + (long)g * aG;
    int m0 = blockIdx.y * 64, n0 = blockIdx.x * 64;
    int tid = threadIdx.x, tx = tid & 15, ty = tid >> 4;
    float acc[4][4][4] = {};

    int am = tid >> 2, ak = (tid & 3) * 4;
    int bk = tid >> 4, bn = (tid & 15) * 4;
    const float* Bp[4];
    #pragma unroll
    for (int s = 0; s < 4; s++) Bp[s] = B + (long)(p + 8 * s) * bSlab;

    for (int k0 = 0; k0 < K; k0 += 16) {
        float4 a4 = make_float4(0.f, 0.f, 0.f, 0.f);
        if (m0 + am < M) a4 = *(const float4*)&Ap[(long)(m0 + am) * K + k0 + ak];
        long boff = (long)(k0 + bk) * 256 + n0 + bn;
        float4 bv4[4];
        #pragma unroll
        for (int s = 0; s < 4; s++) bv4[s] = *(const float4*)&Bp[s][boff];
        As[ak + 0][am] = a4.x;
        As[ak + 1][am] = a4.y;
        As[ak + 2][am] = a4.z;
        As[ak + 3][am] = a4.w;
        #pragma unroll
        for (int s = 0; s < 4; s++) *(float4*)&Bs[s][bk][bn] = bv4[s];
        __syncthreads();
        #pragma unroll
        for (int kk = 0; kk < 16; kk++) {
            float4 av4 = *(const float4*)&As[kk][ty * 4];
            float av[4] = {av4.x, av4.y, av4.z, av4.w};
            #pragma unroll
            for (int s = 0; s < 4; s++) {
                float4 b4 = *(const float4*)&Bs[s][kk][tx * 4];
                float bv[4] = {b4.x, b4.y, b4.z, b4.w};
                #pragma unroll
                for (int u = 0; u < 4; u++)
                    #pragma unroll
                    for (int v = 0; v < 4; v++)
                        acc[s][u][v] = fmaf(av[u], bv[v], acc[s][u][v]);
            }
        }
        __syncthreads();
    }

    #pragma unroll
    for (int s = 0; s < 4; s++) {
        long slab = (long)g * 32 + p + 8 * s;
        #pragma unroll
        for (int u = 0; u < 4; u++) {
            int m = m0 + ty * 4 + u;
            if (m >= M) continue;
            float bi = bias  ? bias [g * pG + m]       : 0.f;
            float sc = scale ? scale[g * pG + m] * BNS : 1.f;
            float sh = shift ? shift[g * pG + m]       : 0.f;
            float4 o;
            o.x = (acc[s][u][0] + bi) * sc + sh;
            o.y = (acc[s][u][1] + bi) * sc + sh;
            o.z = (acc[s][u][2] + bi) * sc + sh;
            o.w = (acc[s][u][3] + bi) * sc + sh;
            *(float4*)&C[slab * M * 256 + (long)m * 256 + n0 + tx * 4] = o;
        }
    }
}

// ================= LIF kernels =============================================
__global__ void lif4_kernel(float4* __restrict__ buf, long M4)
{
    long tid = (long)blockIdx.x * blockDim.x + threadIdx.x;
    long total = 8 * M4;
    if (tid >= total) return;
    long j = tid % M4;
    int  b = (int)(tid / M4);
    float4 mem = make_float4(0.f, 0.f, 0.f, 0.f);
    #pragma unroll
    for (int t = 0; t < 4; t++) {
        long idx = (long)(t * 8 + b) * M4 + j;
        float4 x = buf[idx];
        float4 sp;
        mem.x += (x.x - mem.x) * 0.5f; sp.x = (mem.x >= 1.f) ? 1.f : 0.f; mem.x *= (1.f - sp.x);
        mem.y += (x.y - mem.y) * 0.5f; sp.y = (mem.y >= 1.f) ? 1.f : 0.f; mem.y *= (1.f - sp.y);
        mem.z += (x.z - mem.z) * 0.5f; sp.z = (mem.z >= 1.f) ? 1.f : 0.f; mem.z *= (1.f - sp.z);
        mem.w += (x.w - mem.w) * 0.5f; sp.w = (mem.w >= 1.f) ? 1.f : 0.f; mem.w *= (1.f - sp.w);
        buf[idx] = sp;
    }
}

// LIF + add base: outv = base + spike(pre)
__global__ void lif4_add_kernel(const float4* __restrict__ pre, const float4* __restrict__ base,
                                float4* __restrict__ outv, long M4)
{
    long tid = (long)blockIdx.x * blockDim.x + threadIdx.x;
    long total = 8 * M4;
    if (tid >= total) return;
    long j = tid % M4;
    int  b = (int)(tid / M4);
    float4 mem = make_float4(0.f, 0.f, 0.f, 0.f);
    #pragma unroll
    for (int t = 0; t < 4; t++) {
        long idx = (long)(t * 8 + b) * M4 + j;
        float4 x = pre[idx];
        float4 bs = base[idx];
        float4 sp;
        mem.x += (x.x - mem.x) * 0.5f; sp.x = (mem.x >= 1.f) ? 1.f : 0.f; mem.x *= (1.f - sp.x);
        mem.y += (x.y - mem.y) * 0.5f; sp.y = (mem.y >= 1.f) ? 1.f : 0.f; mem.y *= (1.f - sp.y);
        mem.z += (x.z - mem.z) * 0.5f; sp.z = (mem.z >= 1.f) ? 1.f : 0.f; mem.z *= (1.f - sp.z);
        mem.w += (x.w - mem.w) * 0.5f; sp.w = (mem.w >= 1.f) ? 1.f : 0.f; mem.w *= (1.f - sp.w);
        outv[idx] = make_float4(bs.x + sp.x, bs.y + sp.y, bs.z + sp.z, bs.w + sp.w);
    }
}

__global__ void lif_q_kernel()
{
    int tid = blockIdx.x * 256 + threadIdx.x;
    if (tid >= 4*8*96*256) return;
    int n = tid & 255;
    int c = (tid >> 8) % 96;
    int b = (tid / (256*96)) & 7;
    int e = tid / (256*96*8);
    float mem = 0.f;
    #pragma unroll
    for (int t = 0; t < 4; t++) {
        int eb = e*32 + t*8 + b;
        float x = g_q[((long)eb*96 + c)*256 + n];
        mem = mem + (x - mem) * 0.5f;
        unsigned short sp = (mem >= 1.f) ? 0x3F80 : 0;
        mem *= (sp ? 0.f : 1.f);
        g_qb[((long)eb*256 + n)*96 + c] = sp;
    }
}
__global__ void lif_k_kernel()
{
    int tid = blockIdx.x * 256 + threadIdx.x;
    if (tid >= 8*96*256) return;
    int m = tid & 255;
    int c = (tid >> 8) % 96;
    int b = tid / (256*96);
    float mem = 0.f;
    #pragma unroll
    for (int t = 0; t < 4; t++) {
        int tb = t*8 + b;
        float x = g_k[((long)tb*96 + c)*256 + m];
        mem = mem + (x - mem) * 0.5f;
        unsigned short sp = (mem >= 1.f) ? 0x3F80 : 0;
        mem *= (sp ? 0.f : 1.f);
        g_kb[((long)tb*256 + m)*96 + c] = sp;
    }
}
__global__ void lif_v_kernel()
{
    int tid = blockIdx.x * 256 + threadIdx.x;
    if (tid >= 8*384*256) return;
    int m = tid & 255;
    int d = (tid >> 8) % 384;
    int b = tid / (256*384);
    float mem = 0.f;
    #pragma unroll
    for (int t = 0; t < 4; t++) {
        int tb = t*8 + b;
        long idx = ((long)tb*384 + d)*256 + m;
        float x = g_v[idx];
        mem = mem + (x - mem) * 0.5f;
        unsigned short sp = (mem >= 1.f) ? 0x3F80 : 0;
        mem *= (sp ? 0.f : 1.f);
        g_vb[idx] = sp;
    }
}

// ================= attn via mma.sync =======================================
__global__ __launch_bounds__(256) void attn_mma_kernel()
{
    extern __shared__ unsigned short sm[];    // As[128][104], Bs[128][104]
    unsigned short* As = sm;
    unsigned short* Bs = sm + 128*104;
    int mt = blockIdx.x, nt = blockIdx.y, eb = blockIdx.z;
    int tb = eb & 31;
    int tid = threadIdx.x, lane = tid & 31, warp = tid >> 5;

    const uint4* gq = (const uint4*)(g_qb + ((long)eb*256 + nt*128)*96);
    for (int idx = tid; idx < 1536; idx += 256) {
        int i = idx / 12, s = idx % 12;
        *(uint4*)(As + i*104 + s*8) = gq[idx];
    }
    const uint4* gk = (const uint4*)(g_kb + ((long)tb*256 + mt*128)*96);
    for (int idx = tid; idx < 1536; idx += 256) {
        int i = idx / 12, s = idx % 12;
        *(uint4*)(Bs + i*104 + s*8) = gk[idx];
    }
    __syncthreads();

    int wn = (warp >> 2) * 64, wm = (warp & 3) * 32;
    float acc[4][4][4] = {};
    uint32_t base = smem_u32(sm);
    int aRow = lane & 15, aK = (lane >> 4) * 8;
    int bRow = lane & 7,  bK = ((lane >> 3) & 1) * 8;

    #pragma unroll
    for (int kt = 0; kt < 6; kt++) {
        uint32_t a[4][4], bf[4][2];
        #pragma unroll
        for (int r = 0; r < 4; r++) {
            uint32_t ad = base + (uint32_t)(((wn + r*16 + aRow)*104 + kt*16 + aK) * 2);
            LDMX4(a[r][0], a[r][1], a[r][2], a[r][3], ad);
        }
        #pragma unroll
        for (int c = 0; c < 4; c++) {
            uint32_t ad = base + (uint32_t)((128*104 + (wm + c*8 + bRow)*104 + kt*16 + bK) * 2);
            LDMX2(bf[c][0], bf[c][1], ad);
        }
        #pragma unroll
        for (int r = 0; r < 4; r++)
            #pragma unroll
            for (int c = 0; c < 4; c++)
                MMA16816(acc[r][c][0], acc[r][c][1], acc[r][c][2], acc[r][c][3],
                         a[r][0], a[r][1], a[r][2], a[r][3], bf[c][0], bf[c][1]);
    }

    unsigned short* ga = g_ab + (long)eb * 65536;
    #pragma unroll
    for (int r = 0; r < 4; r++) {
        int n = nt*128 + wn + r*16 + (lane >> 2);
        #pragma unroll
        for (int c = 0; c < 4; c++) {
            int m = mt*128 + wm + c*8 + (lane & 3)*2;
            uint32_t p0 = (uint32_t)__bfloat16_as_ushort(__float2bfloat16(acc[r][c][0]))
                        | ((uint32_t)__bfloat16_as_ushort(__float2bfloat16(acc[r][c][1])) << 16);
            uint32_t p1 = (uint32_t)__bfloat16_as_ushort(__float2bfloat16(acc[r][c][2]))
                        | ((uint32_t)__bfloat16_as_ushort(__float2bfloat16(acc[r][c][3])) << 16);
            *(uint32_t*)(ga + (long)n*256 + m)       = p0;
            *(uint32_t*)(ga + (long)(n+8)*256 + m)   = p1;
        }
    }
}

// ================= res via mma.sync ========================================
__global__ __launch_bounds__(256) void res_mma_kernel()
{
    __shared__ unsigned short As[128*72];
    __shared__ unsigned short Bs[128*72];
    int dt = blockIdx.x, nt = blockIdx.y, eb = blockIdx.z;
    int tb = eb & 31;
    int tid = threadIdx.x, lane = tid & 31, warp = tid >> 5;
    int wn = (warp >> 2) * 64, wm = (warp & 3) * 32;
    float acc[4][4][4] = {};
    uint32_t baseA = smem_u32(As), baseB = smem_u32(Bs);
    int aRow = lane & 15, aK = (lane >> 4) * 8;
    int bRow = lane & 7,  bK = ((lane >> 3) & 1) * 8;

    for (int ch = 0; ch < 4; ch++) {
        const uint4* gA = (const uint4*)(g_ab + ((long)eb*256 + nt*128)*256 + ch*64);
        for (int idx = tid; idx < 1024; idx += 256) {
            int i = idx >> 3, s = idx & 7;
            *(uint4*)(As + i*72 + s*8) = gA[i*32 + s];
        }
        const uint4* gB = (const uint4*)(g_vb + ((long)tb*384 + dt*128)*256 + ch*64);
        for (int idx = tid; idx < 1024; idx += 256) {
            int i = idx >> 3, s = idx & 7;
            *(uint4*)(Bs + i*72 + s*8) = gB[i*32 + s];
        }
        __syncthreads();
        #pragma unroll
        for (int kt = 0; kt < 4; kt++) {
            uint32_t a[4][4], bf[4][2];
            #pragma unroll
            for (int r = 0; r < 4; r++) {
                uint32_t ad = baseA + (uint32_t)(((wn + r*16 + aRow)*72 + kt*16 + aK) * 2);
                LDMX4(a[r][0], a[r][1], a[r][2], a[r][3], ad);
            }
            #pragma unroll
            for (int c = 0; c < 4; c++) {
                uint32_t ad = baseB + (uint32_t)(((wm + c*8 + bRow)*72 + kt*16 + bK) * 2);
                LDMX2(bf[c][0], bf[c][1], ad);
            }
            #pragma unroll
            for (int r = 0; r < 4; r++)
                #pragma unroll
                for (int c = 0; c < 4; c++)
                    MMA16816(acc[r][c][0], acc[r][c][1], acc[r][c][2], acc[r][c][3],
                             a[r][0], a[r][1], a[r][2], a[r][3], bf[c][0], bf[c][1]);
        }
        __syncthreads();
    }

    #pragma unroll
    for (int r = 0; r < 4; r++) {
        int n = nt*128 + wn + r*16 + (lane >> 2);
        #pragma unroll
        for (int c = 0; c < 4; c++) {
            int d = dt*128 + wm + c*8 + (lane & 3)*2;
            float2 v0 = make_float2(acc[r][c][0], acc[r][c][1]);
            float2 v1 = make_float2(acc[r][c][2], acc[r][c][3]);
            *(float2*)(g_res + ((long)eb*256 + n)*384 + d)     = v0;
            *(float2*)(g_res + ((long)eb*256 + n + 8)*384 + d) = v1;
        }
    }
}

// ========== exact-fp32 linear via 3-split bf16 mma =========================
__global__ __launch_bounds__(256) void wmma_lin_kernel(
    const unsigned short* __restrict__ A3, const unsigned short* __restrict__ Bb,
    float* __restrict__ outF,
    const float* __restrict__ bias, const float* __restrict__ scale,
    const float* __restrict__ shift, int M, int K)
{
    __shared__ unsigned short As[3*128*40];
    __shared__ unsigned short Bs[128*40];
    int mt = blockIdx.x, nt = blockIdx.y, z = blockIdx.z;
    int tid = threadIdx.x, lane = tid & 31, warp = tid >> 5;
    int m0 = mt * 128;
    int wn = (warp >> 2) * 64, wm = (warp & 3) * 32;
    float acc[4][4][4] = {};
    uint32_t baseA = smem_u32(As), baseB = smem_u32(Bs);
    int aRow = lane & 15, aK = (lane >> 4) * 8;
    int bRow = lane & 7,  bK = ((lane >> 3) & 1) * 8;

    for (int k0 = 0; k0 < K; k0 += 32) {
        for (int idx = tid; idx < 1536; idx += 256) {
            int s = idx / 512, r = idx % 512;
            int i = r >> 2, p4 = r & 3;
            *(uint4*)(As + (s*128 + i)*40 + p4*8) =
                *(const uint4*)(A3 + ((long)s*M + m0 + i)*K + k0 + p4*8);
        }
        for (int idx = tid; idx < 512; idx += 256) {
            int i = idx >> 2, p4 = idx & 3;
            *(uint4*)(Bs + i*40 + p4*8) =
                *(const uint4*)(Bb + ((long)z*256 + nt*128 + i)*K + k0 + p4*8);
        }
        __syncthreads();
        #pragma unroll
        for (int kt = 0; kt < 2; kt++) {
            uint32_t bf[4][2];
            #pragma unroll
            for (int c = 0; c < 4; c++) {
                uint32_t ad = baseB + (uint32_t)(((wm + c*8 + bRow)*40 + kt*16 + bK) * 2);
                LDMX2(bf[c][0], bf[c][1], ad);
            }
            #pragma unroll
            for (int s = 0; s < 3; s++) {
                uint32_t a[4][4];
                #pragma unroll
                for (int r = 0; r < 4; r++) {
                    uint32_t ad = baseA + (uint32_t)(((s*128 + wn + r*16 + aRow)*40 + kt*16 + aK) * 2);
                    LDMX4(a[r][0], a[r][1], a[r][2], a[r][3], ad);
                }
                #pragma unroll
                for (int r = 0; r < 4; r++)
                    #pragma unroll
                    for (int c = 0; c < 4; c++)
                        MMA16816(acc[r][c][0], acc[r][c][1], acc[r][c][2], acc[r][c][3],
                                 a[r][0], a[r][1], a[r][2], a[r][3], bf[c][0], bf[c][1]);
            }
        }
        __syncthreads();
    }

    #pragma unroll
    for (int r = 0; r < 4; r++) {
        int m  = m0 + wn + r*16 + (lane >> 2);
        float bi0 = bias[m],   sc0 = scale[m]   * BNS, sh0 = shift[m];
        float bi1 = bias[m+8], sc1 = scale[m+8] * BNS, sh1 = shift[m+8];
        #pragma unroll
        for (int c = 0; c < 4; c++) {
            int n = nt*128 + wm + c*8 + (lane & 3)*2;
            float2 v0, v1;
            v0.x = (acc[r][c][0] + bi0) * sc0 + sh0;
            v0.y = (acc[r][c][1] + bi0) * sc0 + sh0;
            v1.x = (acc[r][c][2] + bi1) * sc1 + sh1;
            v1.y = (acc[r][c][3] + bi1) * sc1 + sh1;
            *(float2*)(outF + ((long)z*M + m)*256 + n)     = v0;
            *(float2*)(outF + ((long)z*M + m + 8)*256 + n) = v1;
        }
    }
}

// ================= helper kernels ==========================================
__global__ void wsplit3_kernel(const float* __restrict__ w, unsigned short* __restrict__ w3, int total)
{
    int i = blockIdx.x * 256 + threadIdx.x;
    if (i >= total) return;
    float x = w[i];
    __nv_bfloat16 h0 = __float2bfloat16(x);
    float r1 = x - __bfloat162float(h0);
    __nv_bfloat16 h1 = __float2bfloat16(r1);
    float r2 = r1 - __bfloat162float(h1);
    __nv_bfloat16 h2 = __float2bfloat16(r2);
    w3[i]             = __bfloat16_as_ushort(h0);
    w3[total + i]     = __bfloat16_as_ushort(h1);
    w3[2 * total + i] = __bfloat16_as_ushort(h2);
}

// fused res-LIF + router combine: reads res PRE-acts, emits bf16 y (exact ints)
__global__ void combine_lif_kernel()
{
    long tid = (long)blockIdx.x * 256 + threadIdx.x;
    if (tid >= (long)8 * 256 * 384) return;
    int d = (int)(tid % 384);
    int n = (int)((tid / 384) % 256);
    int b = (int)(tid / (384 * 256));
    float y[4] = {0.f, 0.f, 0.f, 0.f};
    #pragma unroll
    for (int e = 0; e < 4; e++) {
        float mem = 0.f;
        #pragma unroll
        for (int t = 0; t < 4; t++) {
            int eb = e * 32 + t * 8 + b;
            float pre = g_res[((long)eb * 256 + n) * 384 + d];
            mem = mem + (pre - mem) * 0.5f;
            float sp = (mem >= 1.f) ? 1.f : 0.f;
            mem *= (1.f - sp);
            y[t] = fmaf(g_w[((t * 8 + b) * 4 + e) * 256 + n], sp, y[t]);
        }
    }
    #pragma unroll
    for (int t = 0; t < 4; t++)
        g_yb[((long)(t * 8 + b) * 256 + n) * 384 + d] =
            __bfloat16_as_ushort(__float2bfloat16(y[t]));
}

__global__ void transpose_m_kernel()
{
    __shared__ unsigned short tile[32][33];
    int c0 = blockIdx.x * 32, n0 = blockIdx.y * 32, tb = blockIdx.z;
    int tx = threadIdx.x & 31, ty = threadIdx.x >> 5;
    #pragma unroll
    for (int p = 0; p < 4; p++) {
        int c = c0 + ty + p*8;
        tile[ty + p*8][tx] = __bfloat16_as_ushort(
            __float2bfloat16(g_m[((long)tb*1024 + c)*256 + n0 + tx]));
    }
    __syncthreads();
    #pragma unroll
    for (int p = 0; p < 4; p++) {
        int n = n0 + ty + p*8;
        g_mb[((long)tb*256 + n)*1024 + c0 + tx] = tile[tx][ty + p*8];
    }
}

__global__ void dwconv_gate_kernel(const float* __restrict__ dw_w, const float* __restrict__ dw_b,
                                   const float* __restrict__ dw_g, const float* __restrict__ dw_be)
{
    int tid = blockIdx.x * 256 + threadIdx.x;
    if (tid >= 8 * 1024 * 256) return;
    int n  = tid & 255;
    int c  = (tid >> 8) & 1023;
    int b  = tid >> 18;
    int hh = n >> 4, ww = n & 15;
    float wk[9];
    #pragma unroll
    for (int i = 0; i < 9; i++) wk[i] = dw_w[c * 9 + i];
    float bi = dw_b[c], sc = dw_g[c] * BNS, sh = dw_be[c];
    float mem = 0.f;
    #pragma unroll
    for (int t = 0; t < 4; t++) {
        int tb = t * 8 + b;
        const float* x1 = g_h + ((long)tb * 2048 + c) * 256;
        float acc = bi;
        #pragma unroll
        for (int di = 0; di < 3; di++) {
            int yy = hh + di - 1;
            if (yy < 0 || yy > 15) continue;
            #pragma unroll
            for (int dj = 0; dj < 3; dj++) {
                int xx = ww + dj - 1;
                if (xx < 0 || xx > 15) continue;
                acc = fmaf(wk[di * 3 + dj], x1[yy * 16 + xx], acc);
            }
        }
        float pre = acc * sc + sh;
        mem = mem + (pre - mem) * 0.5f;
        float sp = (mem >= 1.f) ? 1.f : 0.f;
        mem *= (1.f - sp);
        float x2 = g_h[((long)tb * 2048 + 1024 + c) * 256 + n];
        g_m[((long)tb * 1024 + c) * 256 + n] = sp * x2;
    }
}

// ===========================================================================
extern "C" void kernel_launch(void* const* d_in, const int* in_sizes, int n_in,
                              void* d_out, int out_size)
{
    const float* x         = (const float*)d_in[0];
    const float* k_w       = (const float*)d_in[2];
    const float* v_w       = (const float*)d_in[3];
    const float* router_w  = (const float*)d_in[4];
    const float* router_b  = (const float*)d_in[5];
    const float* router_g  = (const float*)d_in[6];
    const float* router_be = (const float*)d_in[7];
    const float* exp_w     = (const float*)d_in[8];
    const float* exp_g     = (const float*)d_in[9];
    const float* exp_b     = (const float*)d_in[10];
    const float* proj_w    = (const float*)d_in[11];
    const float* proj_b    = (const float*)d_in[12];
    const float* proj_g    = (const float*)d_in[13];
    const float* proj_be   = (const float*)d_in[14];
    const float* fc1_w     = (const float*)d_in[15];
    const float* fc1_b     = (const float*)d_in[16];
    const float* fc1_g     = (const float*)d_in[17];
    const float* fc1_be    = (const float*)d_in[18];
    const float* dw_w      = (const float*)d_in[19];
    const float* dw_b      = (const float*)d_in[20];
    const float* dw_g      = (const float*)d_in[21];
    const float* dw_be     = (const float*)d_in[22];
    const float* fc2_w     = (const float*)d_in[23];
    const float* fc2_b     = (const float*)d_in[24];
    const float* fc2_g     = (const float*)d_in[25];
    const float* fc2_be    = (const float*)d_in[26];
    float* out = (float*)d_out;

    float *pk, *pv, *pw, *pq, *pp, *pxr, *ph, *pm, *pf2, *pres;
    unsigned short *pqb, *pkb, *pvb, *pyb, *pmb, *pw3a, *pw3b;
    cudaGetSymbolAddress((void**)&pk,   g_k);
    cudaGetSymbolAddress((void**)&pv,   g_v);
    cudaGetSymbolAddress((void**)&pw,   g_w);
    cudaGetSymbolAddress((void**)&pq,   g_q);
    cudaGetSymbolAddress((void**)&pres, g_res);
    cudaGetSymbolAddress((void**)&pp,   g_p);
    cudaGetSymbolAddress((void**)&pxr,  g_xr);
    cudaGetSymbolAddress((void**)&ph,   g_h);
    cudaGetSymbolAddress((void**)&pm,   g_m);
    cudaGetSymbolAddress((void**)&pf2,  g_f2);
    cudaGetSymbolAddress((void**)&pqb,  g_qb);
    cudaGetSymbolAddress((void**)&pkb,  g_kb);
    cudaGetSymbolAddress((void**)&pvb,  g_vb);
    cudaGetSymbolAddress((void**)&pyb,  g_yb);
    cudaGetSymbolAddress((void**)&pmb,  g_mb);
    cudaGetSymbolAddress((void**)&pw3a, g_w3a);
    cudaGetSymbolAddress((void**)&pw3b, g_w3b);

    cudaFuncSetAttribute(attn_mma_kernel, cudaFuncAttributeMaxDynamicSharedMemorySize, 53248);

    const long XB = 384 * 256;
    dim3 blk(256);

    // weight splits
    wsplit3_kernel<<<(384*384+255)/256,blk>>>(proj_w, pw3a, 384*384);
    wsplit3_kernel<<<(384*1024+255)/256,blk>>>(fc2_w, pw3b, 384*1024);

    // --- SSA pre-activations ---
    gemm_z2_kernel<<<dim3(4,2,16),blk>>>(k_w,0, x,XB,
        pk, nullptr,nullptr,nullptr,0, 96,384);
    gemm_z2_kernel<<<dim3(4,6,16),blk>>>(v_w,0, x,XB,
        pv, nullptr,nullptr,nullptr,0, 384,384);
    gemm_z2_kernel<<<dim3(4,1,16),blk>>>(router_w,0, x,XB,
        pw, router_b,router_g,router_be,0, 4,384);
    gemm_z4_kernel<<<dim3(4,2,32),blk>>>(exp_w,(long)96*384, x,XB,
        pq, nullptr,exp_g,exp_b,96, 96,384);

    // --- LIF -> bf16 spikes in mma layouts ---
    lif_k_kernel<<<(8*96*256+255)/256,blk>>>();
    lif_v_kernel<<<(8*384*256+255)/256,blk>>>();
    lif4_kernel<<<(8*256+255)/256,blk>>>((float4*)pw, 256);
    lif_q_kernel<<<(4*8*96*256+255)/256,blk>>>();

    // --- tensor-core attention ---
    attn_mma_kernel<<<dim3(2,2,128),blk,53248>>>();
    res_mma_kernel<<<dim3(3,2,128),blk>>>();

    // fused res-LIF + combine -> bf16 y
    combine_lif_kernel<<<(8*256*384+255)/256,blk>>>();

    // proj on tensor cores -> pre-acts; fused LIF+residual: xr = x + spike(p)
    wmma_lin_kernel<<<dim3(3,2,32),blk>>>(pw3a, pyb, pp, proj_b, proj_g, proj_be, 384, 384);
    lif4_add_kernel<<<(8*24576+255)/256,blk>>>((const float4*)pp, (const float4*)x,
                                               (float4*)pxr, 24576);

    // --- MLP ---
    gemm_z4_kernel<<<dim3(4,32,8),blk>>>(fc1_w,0, pxr,XB,
        ph, fc1_b,fc1_g,fc1_be,0, 2048,384);
    lif4_kernel<<<(8*131072+255)/256,blk>>>((float4*)ph, 131072);
    dwconv_gate_kernel<<<(8*1024*256+255)/256,blk>>>(dw_w, dw_b, dw_g, dw_be);
    transpose_m_kernel<<<dim3(32,8,32),blk>>>();

    // fc2 on tensor cores -> pre-acts; fused LIF+residual: out = xr + spike(f2)
    wmma_lin_kernel<<<dim3(3,2,32),blk>>>(pw3b, pmb, pf2, fc2_b, fc2_g, fc2_be, 384, 1024);
    lif4_add_kernel<<<(8*24576+255)/256,blk>>>((const float4*)pf2, (const float4*)pxr,
                                               (float4*)out, 24576);
}